// round 13
// baseline (speedup 1.0000x reference)
#include <cuda_runtime.h>
#include <cuda_bf16.h>
#include <mma.h>
#include <cstdint>

using namespace nvcuda;

// ---------------- problem constants ----------------
#define T_LEN   128
#define E_DIM   768
#define H1      128
#define H2      64
#define G1      512   // 4*H1
#define G2      256   // 4*H2
#define NSEQ    920
#define MROWS   (NSEQ * T_LEN)   // 117760
#define SEQ_PER_BLOCK 8
#define LSTM_THREADS  1024

#define ROW_SUP_END 25600
#define ROW_QRY_END 51200
#define ROW_UNL_END 116736

// ---------------- scratch ----------------
__device__ float g_xw1[(long)MROWS * G1];   // 241 MB
__device__ float g_enc[NSEQ * H2];

// ---------------- helpers ----------------
typedef unsigned long long u64t;

__device__ __forceinline__ float tanh_ap(float x) {
    float y; asm("tanh.approx.f32 %0, %1;" : "=f"(y) : "f"(x)); return y;
}
__device__ __forceinline__ float fsig(float x) {
    return fmaf(tanh_ap(0.5f * x), 0.5f, 0.5f);
}
__device__ __forceinline__ u64t ffma2p(u64t a, u64t b, u64t c) {
    u64t d;
    asm("fma.rn.f32x2 %0, %1, %2, %3;" : "=l"(d) : "l"(a), "l"(b), "l"(c));
    return d;
}
__device__ __forceinline__ u64t pack2(float x, float y) {
    u64t d; asm("mov.b64 %0, {%1, %2};" : "=l"(d) : "f"(x), "f"(y)); return d;
}
__device__ __forceinline__ void unpack2(u64t v, float& x, float& y) {
    asm("mov.b64 {%0, %1}, %2;" : "=f"(x), "=f"(y) : "l"(v));
}
__device__ __forceinline__ void cp16(void* smemDst, const void* gmemSrc) {
    unsigned sa = (unsigned)__cvta_generic_to_shared(smemDst);
    asm volatile("cp.async.cg.shared.global [%0], [%1], 16;\n" :: "r"(sa), "l"(gmemSrc));
}
#define CP_COMMIT() asm volatile("cp.async.commit_group;\n" ::)

// =====================================================================
// Kernel 1: xw1 = X @ W1 (unchanged from R11/R12 best)
// =====================================================================
#define BM 128
#define BN 128
#define BK 32
#define ASTRIDE 40
#define BSTRIDE 136
#define STAGE_FLOATS (BM*ASTRIDE + BK*BSTRIDE)           // 9472
#define GEMM_SMEM_FLOATS (3 * STAGE_FLOATS)              // 28416
#define GEMM_SMEM_BYTES  (GEMM_SMEM_FLOATS * 4)          // 113664

__global__ __launch_bounds__(256, 2) void gemm1_kernel(
    const float* __restrict__ support,
    const float* __restrict__ query,
    const float* __restrict__ unlabel,
    const float* __restrict__ model,
    const float* __restrict__ W1)
{
    extern __shared__ float gsm[];

    const int bn = blockIdx.x;
    const int bm = blockIdx.y;
    const long row0 = (long)bm * BM;

    const float* A;
    long arow;
    if (row0 < ROW_SUP_END)      { A = support; arow = row0; }
    else if (row0 < ROW_QRY_END) { A = query;   arow = row0 - ROW_SUP_END; }
    else if (row0 < ROW_UNL_END) { A = unlabel; arow = row0 - ROW_QRY_END; }
    else                         { A = model;   arow = row0 - ROW_UNL_END; }
    const float* Abase = A + arow * E_DIM;

    const int tid  = threadIdx.x;
    const int warp = tid >> 5;
    const int wm   = warp & 3;
    const int wn   = warp >> 2;

    wmma::fragment<wmma::accumulator, 16, 16, 8, float> cf[2][4];
    #pragma unroll
    for (int i = 0; i < 2; i++)
        #pragma unroll
        for (int jj = 0; jj < 4; jj++)
            wmma::fill_fragment(cf[i][jj], 0.0f);

    auto load_stage = [&](int st, int k0) {
        float* Ad = gsm + st * STAGE_FLOATS;
        float* Bd = Ad + BM * ASTRIDE;
        #pragma unroll
        for (int i = 0; i < 4; i++) {
            int idx = tid + i * 256;
            int r = idx >> 3, c = (idx & 7) * 4;
            cp16(&Ad[r * ASTRIDE + c], Abase + (long)r * E_DIM + k0 + c);
        }
        #pragma unroll
        for (int i = 0; i < 4; i++) {
            int idx = tid + i * 256;
            int r = idx >> 5, c = (idx & 31) * 4;
            cp16(&Bd[r * BSTRIDE + c], W1 + (long)(k0 + r) * G1 + bn * BN + c);
        }
        CP_COMMIT();
    };

    load_stage(0, 0);
    load_stage(1, BK);

    const int NKT = E_DIM / BK;
    int st = 0;
    for (int kt = 0; kt < NKT; kt++) {
        if (kt < NKT - 1) asm volatile("cp.async.wait_group 1;\n" ::);
        else              asm volatile("cp.async.wait_group 0;\n" ::);
        __syncthreads();

        if (kt + 2 < NKT) {
            int st2 = st + 2; if (st2 >= 3) st2 -= 3;
            load_stage(st2, (kt + 2) * BK);
        }

        const float* Ac = gsm + st * STAGE_FLOATS;
        const float* Bc = Ac + BM * ASTRIDE;
        #pragma unroll
        for (int kk = 0; kk < 4; kk++) {
            wmma::fragment<wmma::matrix_a, 16, 16, 8, wmma::precision::tf32, wmma::row_major> af[2];
            #pragma unroll
            for (int i = 0; i < 2; i++)
                wmma::load_matrix_sync(af[i], &Ac[(wm * 32 + i * 16) * ASTRIDE + kk * 8], ASTRIDE);
            #pragma unroll
            for (int jj = 0; jj < 4; jj++) {
                wmma::fragment<wmma::matrix_b, 16, 16, 8, wmma::precision::tf32, wmma::row_major> bf;
                wmma::load_matrix_sync(bf, &Bc[(kk * 8) * BSTRIDE + wn * 64 + jj * 16], BSTRIDE);
                #pragma unroll
                for (int i = 0; i < 2; i++)
                    wmma::mma_sync(cf[i][jj], af[i], bf, cf[i][jj]);
            }
        }
        if (++st >= 3) st -= 3;
    }

    #pragma unroll
    for (int i = 0; i < 2; i++)
        #pragma unroll
        for (int jj = 0; jj < 4; jj++) {
            float* dst = &g_xw1[(row0 + wm * 32 + i * 16) * (long)G1 + bn * BN + wn * 64 + jj * 16];
            wmma::store_matrix_sync(dst, cf[i][jj], G1, wmma::mem_row_major);
        }
}

// =====================================================================
// Kernel 2: fused LSTM1+LSTM2, merged phases, 1024 THREADS (8 warps/SMSP).
// Same total work as R12; per-thread work halved:
//   Phase A: thread = (gate j=tid&511, seq group g=tid>>9 -> 4 seqs)
//   Phase B: thread = (gate j2=tid&255, seq group sg=tid>>8 -> 2 seqs)
//   update1: 1 state/thread (seq=tid>>7, n=tid&127)
//   update2: tid<512 (seq=tid>>6, n=tid&63)
// smem layout identical to R12 (227328 B).
// =====================================================================
#define LSTM_SMEM_FLOATS 56832
#define LSTM_SMEM_BYTES  (LSTM_SMEM_FLOATS * 4)

__global__ __launch_bounds__(LSTM_THREADS) void lstm_kernel(
    const float* __restrict__ U1,
    const float* __restrict__ b1,
    const float* __restrict__ W2,
    const float* __restrict__ U2,
    const float* __restrict__ b2)
{
    extern __shared__ float sm[];
    float* sW2   = sm;
    float* sU2   = sm + 32768;
    float* zbufA = sm + 49152;
    float* zbufB = sm + 53248;
    float* h1T   = sm + 55296;
    float* h2T   = sm + 56320;

    const int tid = threadIdx.x;
    const long qbase = (long)blockIdx.x * SEQ_PER_BLOCK;

    {
        const float4* s4 = (const float4*)W2;
        float4* d4 = (float4*)sW2;
        for (int i = tid; i < (H1 * G2) / 4; i += LSTM_THREADS) d4[i] = s4[i];
        s4 = (const float4*)U2; d4 = (float4*)sU2;
        for (int i = tid; i < (H2 * G2) / 4; i += LSTM_THREADS) d4[i] = s4[i];
        if (tid < 64 * 8) h2T[tid] = 0.0f;
    }

    // ---- thread mappings ----
    const int j   = tid & 511;        // Phase A gate col
    const int g   = tid >> 9;         // Phase A seq group (0/1) -> seqs 4g..4g+3
    const int j2  = tid & 255;        // Phase B gate col
    const int sg  = tid >> 8;         // Phase B seq group (0..3) -> seqs 2sg,2sg+1
    const int us1 = tid >> 7, un1 = tid & 127;   // update1: 1 state
    const int us2 = tid >> 6, un2 = tid & 63;    // update2 (tid<512)

    float c1 = 0.0f, c2 = 0.0f;

    const float bb  = b1[j];
    const float b2v = b2[j2];
    const u64t  b2p = pack2(b2v, b2v);

    // xw1 base for this thread's Phase-A seqs
    const float* xpA = g_xw1 + ((qbase + 4 * g) * T_LEN) * (long)G1 + j;
    const float* U1j = U1 + j;

    __syncthreads();   // weights + h2T init visible

    // ---- prologue: z1(0) = xw(0) + b1   (h1(-1) = 0) ----
    #pragma unroll
    for (int s = 0; s < 4; s++)
        zbufA[(4 * g + s) * G1 + j] = xpA[(long)s * T_LEN * G1] + bb;
    __syncthreads();
    // update1(0) -> h1(0)
    {
        const float* zb = &zbufA[us1 * G1];
        float zi = zb[un1], zf = zb[128 + un1], zg = zb[256 + un1], zo = zb[384 + un1];
        c1 = fsig(zf) * c1 + fsig(zi) * tanh_ap(zg);
        h1T[un1 * 8 + us1] = fsig(zo) * tanh_ap(c1);
    }
    __syncthreads();

    for (int t = 0; t < T_LEN; t++) {
        const bool notlast = (t < T_LEN - 1);

        // xw1 loads for t+1 (DRAM; issued first, consumed last)
        float xv[4];
        if (notlast) {
            const float* xp = xpA + (long)(t + 1) * G1;
            #pragma unroll
            for (int s = 0; s < 4; s++) xv[s] = xp[(long)s * T_LEN * G1];
        }

        // ---- matvec B: z2(t) = b2 + h1(t)@W2 + h2(t-1)@U2  (2 seqs) ----
        u64t acc2 = b2p;
        #pragma unroll 8
        for (int k = 0; k < H1; k++) {
            u64t hv = *(const u64t*)&h1T[k * 8 + 2 * sg];
            float wv = sW2[k * G2 + j2];
            acc2 = ffma2p(hv, pack2(wv, wv), acc2);
        }
        #pragma unroll 8
        for (int k = 0; k < H2; k++) {
            u64t hv = *(const u64t*)&h2T[k * 8 + 2 * sg];
            float uv = sU2[k * G2 + j2];
            acc2 = ffma2p(hv, pack2(uv, uv), acc2);
        }

        // ---- matvec A: z1(t+1) = h1(t)@U1  (4 seqs) ----
        u64t a01 = 0ull, a23 = 0ull;
        if (notlast) {
            #pragma unroll 1
            for (int kb = 0; kb < H1; kb += 16) {
                float u[16];
                #pragma unroll
                for (int i = 0; i < 16; i++) u[i] = U1j[(kb + i) * G1];
                #pragma unroll
                for (int i = 0; i < 16; i++) {
                    ulonglong2 hv = *(const ulonglong2*)&h1T[(kb + i) * 8 + 4 * g];
                    u64t uu = pack2(u[i], u[i]);
                    a01 = ffma2p(hv.x, uu, a01);
                    a23 = ffma2p(hv.y, uu, a23);
                }
            }
        }

        // ---- stores ----
        {
            float y0, y1;
            unpack2(acc2, y0, y1);
            zbufB[(2 * sg + 0) * G2 + j2] = y0;
            zbufB[(2 * sg + 1) * G2 + j2] = y1;
        }
        if (notlast) {
            float z0, z1, z2, z3;
            unpack2(a01, z0, z1); unpack2(a23, z2, z3);
            zbufA[(4 * g + 0) * G1 + j] = z0 + xv[0] + bb;
            zbufA[(4 * g + 1) * G1 + j] = z1 + xv[1] + bb;
            zbufA[(4 * g + 2) * G1 + j] = z2 + xv[2] + bb;
            zbufA[(4 * g + 3) * G1 + j] = z3 + xv[3] + bb;
        }
        __syncthreads();

        // ---- update2(t): h2(t), c2  (tid < 512) ----
        if (tid < 512) {
            const float* zb = &zbufB[us2 * G2];
            float zi = zb[un2], zf = zb[64 + un2], zg = zb[128 + un2], zo = zb[192 + un2];
            c2 = fsig(zf) * c2 + fsig(zi) * tanh_ap(zg);
            h2T[un2 * 8 + us2] = fsig(zo) * tanh_ap(c2);
        }
        // ---- update1(t+1): h1(t+1), c1  (all threads) ----
        if (notlast) {
            const float* zb = &zbufA[us1 * G1];
            float zi = zb[un1], zf = zb[128 + un1], zg = zb[256 + un1], zo = zb[384 + un1];
            c1 = fsig(zf) * c1 + fsig(zi) * tanh_ap(zg);
            h1T[un1 * 8 + us1] = fsig(zo) * tanh_ap(c1);
        }
        __syncthreads();
    }

    if (tid < 512)
        g_enc[(qbase + us2) * H2 + un2] = h2T[un2 * 8 + us2];
}

// =====================================================================
// Kernel 3: ALL heads in one launch (unchanged)
// =====================================================================
__global__ __launch_bounds__(128) void heads_kernel(
    const float* __restrict__ W1h, const float* __restrict__ b1h,
    const float* __restrict__ g1h, const float* __restrict__ be1,
    const float* __restrict__ m1h, const float* __restrict__ v1h,
    const float* __restrict__ W2h, const float* __restrict__ b2h,
    const float* __restrict__ g2h, const float* __restrict__ be2,
    const float* __restrict__ m2h, const float* __restrict__ v2h,
    const float* __restrict__ W3h, const float* __restrict__ b3h,
    const float* __restrict__ g3h, const float* __restrict__ be3,
    const float* __restrict__ m3h, const float* __restrict__ v3h,
    float* __restrict__ out)
{
    __shared__ float x[128];
    const int row = blockIdx.x;
    const int tid = threadIdx.x;

    const float *W, *b, *g, *beta, *m, *v;
    int bidx;
    if (row < 200)      { W = W1h; b = b1h; g = g1h; beta = be1; m = m1h; v = v1h; bidx = row / 25; }
    else if (row < 400) { W = W2h; b = b2h; g = g2h; beta = be2; m = m2h; v = v2h; bidx = (row - 200) / 25; }
    else                { W = W3h; b = b3h; g = g3h; beta = be3; m = m3h; v = v3h; bidx = (row - 400) / 64; }

    if (tid < 64) x[tid] = g_enc[row * H2 + tid];
    else          x[tid] = g_enc[(912 + bidx) * H2 + (tid - 64)];
    __syncthreads();

    if (tid < 32) {
        float acc = b[tid];
        #pragma unroll 8
        for (int k = 0; k < 128; k++) acc = fmaf(x[k], W[k * 32 + tid], acc);
        float y = fmaxf(acc, 0.0f);
        out[row * 32 + tid] = g[tid] * (y - m[tid]) * rsqrtf(v[tid] + 1e-3f) + beta[tid];
    }
}

// =====================================================================
extern "C" void kernel_launch(void* const* d_in, const int* in_sizes, int n_in,
                              void* d_out, int out_size)
{
    (void)in_sizes; (void)n_in; (void)out_size;

    const float* support = (const float*)d_in[0];
    const float* query   = (const float*)d_in[1];
    const float* unlabel = (const float*)d_in[2];
    const float* model   = (const float*)d_in[3];
    const float* W1 = (const float*)d_in[4];
    const float* U1 = (const float*)d_in[5];
    const float* b1 = (const float*)d_in[6];
    const float* W2 = (const float*)d_in[7];
    const float* U2 = (const float*)d_in[8];
    const float* b2 = (const float*)d_in[9];
    float* out = (float*)d_out;

    cudaFuncSetAttribute(gemm1_kernel,
                         cudaFuncAttributeMaxDynamicSharedMemorySize,
                         GEMM_SMEM_BYTES);
    dim3 ggrid(G1 / BN, MROWS / BM);   // (4, 920)
    gemm1_kernel<<<ggrid, 256, GEMM_SMEM_BYTES>>>(support, query, unlabel, model, W1);

    cudaFuncSetAttribute(lstm_kernel,
                         cudaFuncAttributeMaxDynamicSharedMemorySize,
                         LSTM_SMEM_BYTES);
    lstm_kernel<<<NSEQ / SEQ_PER_BLOCK, LSTM_THREADS, LSTM_SMEM_BYTES>>>(
        U1, b1, W2, U2, b2);

    heads_kernel<<<912, 128>>>(
        (const float*)d_in[10], (const float*)d_in[11], (const float*)d_in[12],
        (const float*)d_in[13], (const float*)d_in[14], (const float*)d_in[15],
        (const float*)d_in[16], (const float*)d_in[17], (const float*)d_in[18],
        (const float*)d_in[19], (const float*)d_in[20], (const float*)d_in[21],
        (const float*)d_in[22], (const float*)d_in[23], (const float*)d_in[24],
        (const float*)d_in[25], (const float*)d_in[26], (const float*)d_in[27],
        out);
}

// round 14
// speedup vs baseline: 1.3724x; 1.3724x over previous
#include <cuda_runtime.h>
#include <cuda_bf16.h>
#include <mma.h>
#include <cstdint>

using namespace nvcuda;

// ---------------- problem constants ----------------
#define T_LEN   128
#define E_DIM   768
#define H1      128
#define H2      64
#define G1      512   // 4*H1
#define G2      256   // 4*H2
#define NSEQ    920
#define MROWS   (NSEQ * T_LEN)   // 117760
#define SEQ_PER_BLOCK 8
#define LSTM_THREADS  512

#define ROW_SUP_END 25600
#define ROW_QRY_END 51200
#define ROW_UNL_END 116736

// ---------------- scratch ----------------
__device__ float g_xw1[(long)MROWS * G1];   // 241 MB
__device__ float g_enc[NSEQ * H2];

// ---------------- helpers ----------------
typedef unsigned long long u64t;

__device__ __forceinline__ float tanh_ap(float x) {
    float y; asm("tanh.approx.f32 %0, %1;" : "=f"(y) : "f"(x)); return y;
}
__device__ __forceinline__ float fsig(float x) {
    return fmaf(tanh_ap(0.5f * x), 0.5f, 0.5f);
}
__device__ __forceinline__ u64t ffma2p(u64t a, u64t b, u64t c) {
    u64t d;
    asm("fma.rn.f32x2 %0, %1, %2, %3;" : "=l"(d) : "l"(a), "l"(b), "l"(c));
    return d;
}
__device__ __forceinline__ u64t pack2(float x, float y) {
    u64t d; asm("mov.b64 %0, {%1, %2};" : "=l"(d) : "f"(x), "f"(y)); return d;
}
__device__ __forceinline__ void unpack2(u64t v, float& x, float& y) {
    asm("mov.b64 {%0, %1}, %2;" : "=f"(x), "=f"(y) : "l"(v));
}
__device__ __forceinline__ void cp16(void* smemDst, const void* gmemSrc) {
    unsigned sa = (unsigned)__cvta_generic_to_shared(smemDst);
    asm volatile("cp.async.cg.shared.global [%0], [%1], 16;\n" :: "r"(sa), "l"(gmemSrc));
}
#define CP_COMMIT() asm volatile("cp.async.commit_group;\n" ::)

// =====================================================================
// Kernel 1: xw1 = X @ W1 (unchanged from R11/R12 best)
// =====================================================================
#define BM 128
#define BN 128
#define BK 32
#define ASTRIDE 40
#define BSTRIDE 136
#define STAGE_FLOATS (BM*ASTRIDE + BK*BSTRIDE)           // 9472
#define GEMM_SMEM_FLOATS (3 * STAGE_FLOATS)              // 28416
#define GEMM_SMEM_BYTES  (GEMM_SMEM_FLOATS * 4)          // 113664

__global__ __launch_bounds__(256, 2) void gemm1_kernel(
    const float* __restrict__ support,
    const float* __restrict__ query,
    const float* __restrict__ unlabel,
    const float* __restrict__ model,
    const float* __restrict__ W1)
{
    extern __shared__ float gsm[];

    const int bn = blockIdx.x;
    const int bm = blockIdx.y;
    const long row0 = (long)bm * BM;

    const float* A;
    long arow;
    if (row0 < ROW_SUP_END)      { A = support; arow = row0; }
    else if (row0 < ROW_QRY_END) { A = query;   arow = row0 - ROW_SUP_END; }
    else if (row0 < ROW_UNL_END) { A = unlabel; arow = row0 - ROW_QRY_END; }
    else                         { A = model;   arow = row0 - ROW_UNL_END; }
    const float* Abase = A + arow * E_DIM;

    const int tid  = threadIdx.x;
    const int warp = tid >> 5;
    const int wm   = warp & 3;
    const int wn   = warp >> 2;

    wmma::fragment<wmma::accumulator, 16, 16, 8, float> cf[2][4];
    #pragma unroll
    for (int i = 0; i < 2; i++)
        #pragma unroll
        for (int jj = 0; jj < 4; jj++)
            wmma::fill_fragment(cf[i][jj], 0.0f);

    auto load_stage = [&](int st, int k0) {
        float* Ad = gsm + st * STAGE_FLOATS;
        float* Bd = Ad + BM * ASTRIDE;
        #pragma unroll
        for (int i = 0; i < 4; i++) {
            int idx = tid + i * 256;
            int r = idx >> 3, c = (idx & 7) * 4;
            cp16(&Ad[r * ASTRIDE + c], Abase + (long)r * E_DIM + k0 + c);
        }
        #pragma unroll
        for (int i = 0; i < 4; i++) {
            int idx = tid + i * 256;
            int r = idx >> 5, c = (idx & 31) * 4;
            cp16(&Bd[r * BSTRIDE + c], W1 + (long)(k0 + r) * G1 + bn * BN + c);
        }
        CP_COMMIT();
    };

    load_stage(0, 0);
    load_stage(1, BK);

    const int NKT = E_DIM / BK;
    int st = 0;
    for (int kt = 0; kt < NKT; kt++) {
        if (kt < NKT - 1) asm volatile("cp.async.wait_group 1;\n" ::);
        else              asm volatile("cp.async.wait_group 0;\n" ::);
        __syncthreads();

        if (kt + 2 < NKT) {
            int st2 = st + 2; if (st2 >= 3) st2 -= 3;
            load_stage(st2, (kt + 2) * BK);
        }

        const float* Ac = gsm + st * STAGE_FLOATS;
        const float* Bc = Ac + BM * ASTRIDE;
        #pragma unroll
        for (int kk = 0; kk < 4; kk++) {
            wmma::fragment<wmma::matrix_a, 16, 16, 8, wmma::precision::tf32, wmma::row_major> af[2];
            #pragma unroll
            for (int i = 0; i < 2; i++)
                wmma::load_matrix_sync(af[i], &Ac[(wm * 32 + i * 16) * ASTRIDE + kk * 8], ASTRIDE);
            #pragma unroll
            for (int jj = 0; jj < 4; jj++) {
                wmma::fragment<wmma::matrix_b, 16, 16, 8, wmma::precision::tf32, wmma::row_major> bf;
                wmma::load_matrix_sync(bf, &Bc[(kk * 8) * BSTRIDE + wn * 64 + jj * 16], BSTRIDE);
                #pragma unroll
                for (int i = 0; i < 2; i++)
                    wmma::mma_sync(cf[i][jj], af[i], bf, cf[i][jj]);
            }
        }
        if (++st >= 3) st -= 3;
    }

    #pragma unroll
    for (int i = 0; i < 2; i++)
        #pragma unroll
        for (int jj = 0; jj < 4; jj++) {
            float* dst = &g_xw1[(row0 + wm * 32 + i * 16) * (long)G1 + bn * BN + wn * 64 + jj * 16];
            wmma::store_matrix_sync(dst, cf[i][jj], G1, wmma::mem_row_major);
        }
}

// =====================================================================
// Kernel 2: fused LSTM1+LSTM2, merged phases (R12 structure, 512 thr),
// + U1[k=0..63][j] PINNED IN REGISTERS (loaded once; halves per-step
// U1 LDG instructions and L2 traffic).
// smem layout identical to R12 (227328 B).
// =====================================================================
#define LSTM_SMEM_FLOATS 56832
#define LSTM_SMEM_BYTES  (LSTM_SMEM_FLOATS * 4)

__global__ __launch_bounds__(LSTM_THREADS, 1) void lstm_kernel(
    const float* __restrict__ U1,
    const float* __restrict__ b1,
    const float* __restrict__ W2,
    const float* __restrict__ U2,
    const float* __restrict__ b2)
{
    extern __shared__ float sm[];
    float* sW2   = sm;
    float* sU2   = sm + 32768;
    float* zbufA = sm + 49152;
    float* zbufB = sm + 53248;
    float* h1T   = sm + 55296;
    float* h2T   = sm + 56320;

    const int tid = threadIdx.x;
    const long qbase = (long)blockIdx.x * SEQ_PER_BLOCK;

    {
        const float4* s4 = (const float4*)W2;
        float4* d4 = (float4*)sW2;
        for (int i = tid; i < (H1 * G2) / 4; i += LSTM_THREADS) d4[i] = s4[i];
        s4 = (const float4*)U2; d4 = (float4*)sU2;
        for (int i = tid; i < (H2 * G2) / 4; i += LSTM_THREADS) d4[i] = s4[i];
        if (tid < 64 * 8) h2T[tid] = 0.0f;
    }

    float c1a = 0.0f, c1b = 0.0f, c2 = 0.0f;

    const int j  = tid;               // Phase A gate col
    const int j2 = tid & 255;         // Phase B gate col
    const int s0 = (tid >> 8) * 4;    // Phase B seq group

    const int p0s = tid >> 7, p0n = tid & 127;
    const int p1s = 4 + (tid >> 7), p1n = tid & 127;
    const int u2s = tid >> 6, u2n = tid & 63;

    const float* xp0 = g_xw1 + (qbase * T_LEN) * (long)G1 + j;
    const float* U1j = U1 + j;
    const float  bb  = b1[j];
    const float  b2v = b2[j2];
    const u64t   b2p = pack2(b2v, b2v);

    // ---- pin U1[k=0..63][j] in registers (constant across steps) ----
    float u1r[64];
    #pragma unroll
    for (int i = 0; i < 64; i++) u1r[i] = U1j[i * G1];

    __syncthreads();   // weights + h2T init visible

    // ---- prologue: z1(0) = xw(0) + b1   (h1(-1) = 0) ----
    {
        #pragma unroll
        for (int s = 0; s < 8; s++)
            zbufA[s * G1 + j] = xp0[(long)s * T_LEN * G1] + bb;
    }
    __syncthreads();
    // update1(0) -> h1(0)
    {
        const float* zb = &zbufA[p0s * G1];
        float zi = zb[p0n], zf = zb[128 + p0n], zg = zb[256 + p0n], zo = zb[384 + p0n];
        c1a = fsig(zf) * c1a + fsig(zi) * tanh_ap(zg);
        h1T[p0n * 8 + p0s] = fsig(zo) * tanh_ap(c1a);
    }
    {
        const float* zb = &zbufA[p1s * G1];
        float zi = zb[p1n], zf = zb[128 + p1n], zg = zb[256 + p1n], zo = zb[384 + p1n];
        c1b = fsig(zf) * c1b + fsig(zi) * tanh_ap(zg);
        h1T[p1n * 8 + p1s] = fsig(zo) * tanh_ap(c1b);
    }
    __syncthreads();

    for (int t = 0; t < T_LEN; t++) {
        const bool notlast = (t < T_LEN - 1);

        // xw1 loads for t+1 (DRAM; issued first, consumed last)
        float xv[8];
        if (notlast) {
            const float* xp = xp0 + (long)(t + 1) * G1;
            #pragma unroll
            for (int s = 0; s < 8; s++) xv[s] = xp[(long)s * T_LEN * G1];
        }

        // ---- matvec B: z2(t) = b2 + h1(t)@W2 + h2(t-1)@U2 ----
        u64t a2a = b2p, a2b = b2p;
        #pragma unroll 8
        for (int k = 0; k < H1; k++) {
            ulonglong2 hv = *(const ulonglong2*)&h1T[k * 8 + s0];
            float wv = sW2[k * G2 + j2];
            u64t ww = pack2(wv, wv);
            a2a = ffma2p(hv.x, ww, a2a);
            a2b = ffma2p(hv.y, ww, a2b);
        }
        #pragma unroll 8
        for (int k = 0; k < H2; k++) {
            ulonglong2 hv = *(const ulonglong2*)&h2T[k * 8 + s0];
            float uv = sU2[k * G2 + j2];
            u64t uu = pack2(uv, uv);
            a2a = ffma2p(hv.x, uu, a2a);
            a2b = ffma2p(hv.y, uu, a2b);
        }

        // ---- matvec A: z1(t+1) = h1(t)@U1 (+ xw + b later) ----
        u64t a01 = 0ull, a23 = 0ull, a45 = 0ull, a67 = 0ull;
        if (notlast) {
            // k = 0..63 from registers (no LDG)
            #pragma unroll
            for (int i = 0; i < 64; i++) {
                ulonglong2 hA = *(const ulonglong2*)&h1T[i * 8];
                ulonglong2 hB = *(const ulonglong2*)&h1T[i * 8 + 4];
                u64t uu = pack2(u1r[i], u1r[i]);
                a01 = ffma2p(hA.x, uu, a01);
                a23 = ffma2p(hA.y, uu, a23);
                a45 = ffma2p(hB.x, uu, a45);
                a67 = ffma2p(hB.y, uu, a67);
            }
            // k = 64..127 streamed from L2 (register-batched, MLP=16)
            #pragma unroll 1
            for (int kb = 64; kb < H1; kb += 16) {
                float u[16];
                #pragma unroll
                for (int i = 0; i < 16; i++) u[i] = U1j[(kb + i) * G1];
                #pragma unroll
                for (int i = 0; i < 16; i++) {
                    ulonglong2 hA = *(const ulonglong2*)&h1T[(kb + i) * 8];
                    ulonglong2 hB = *(const ulonglong2*)&h1T[(kb + i) * 8 + 4];
                    u64t uu = pack2(u[i], u[i]);
                    a01 = ffma2p(hA.x, uu, a01);
                    a23 = ffma2p(hA.y, uu, a23);
                    a45 = ffma2p(hB.x, uu, a45);
                    a67 = ffma2p(hB.y, uu, a67);
                }
            }
        }

        // ---- stores ----
        {
            float y0, y1, y2, y3;
            unpack2(a2a, y0, y1); unpack2(a2b, y2, y3);
            zbufB[(s0 + 0) * G2 + j2] = y0;
            zbufB[(s0 + 1) * G2 + j2] = y1;
            zbufB[(s0 + 2) * G2 + j2] = y2;
            zbufB[(s0 + 3) * G2 + j2] = y3;
        }
        if (notlast) {
            float z0, z1, z2, z3, z4, z5, z6, z7;
            unpack2(a01, z0, z1); unpack2(a23, z2, z3);
            unpack2(a45, z4, z5); unpack2(a67, z6, z7);
            zbufA[0 * G1 + j] = z0 + xv[0] + bb;
            zbufA[1 * G1 + j] = z1 + xv[1] + bb;
            zbufA[2 * G1 + j] = z2 + xv[2] + bb;
            zbufA[3 * G1 + j] = z3 + xv[3] + bb;
            zbufA[4 * G1 + j] = z4 + xv[4] + bb;
            zbufA[5 * G1 + j] = z5 + xv[5] + bb;
            zbufA[6 * G1 + j] = z6 + xv[6] + bb;
            zbufA[7 * G1 + j] = z7 + xv[7] + bb;
        }
        __syncthreads();

        // ---- update2(t): h2(t), c2 ----
        {
            const float* zb = &zbufB[u2s * G2];
            float zi = zb[u2n], zf = zb[64 + u2n], zg = zb[128 + u2n], zo = zb[192 + u2n];
            c2 = fsig(zf) * c2 + fsig(zi) * tanh_ap(zg);
            h2T[u2n * 8 + u2s] = fsig(zo) * tanh_ap(c2);
        }
        // ---- update1(t+1): h1(t+1), c1 ----
        if (notlast) {
            {
                const float* zb = &zbufA[p0s * G1];
                float zi = zb[p0n], zf = zb[128 + p0n], zg = zb[256 + p0n], zo = zb[384 + p0n];
                c1a = fsig(zf) * c1a + fsig(zi) * tanh_ap(zg);
                h1T[p0n * 8 + p0s] = fsig(zo) * tanh_ap(c1a);
            }
            {
                const float* zb = &zbufA[p1s * G1];
                float zi = zb[p1n], zf = zb[128 + p1n], zg = zb[256 + p1n], zo = zb[384 + p1n];
                c1b = fsig(zf) * c1b + fsig(zi) * tanh_ap(zg);
                h1T[p1n * 8 + p1s] = fsig(zo) * tanh_ap(c1b);
            }
        }
        __syncthreads();
    }

    g_enc[(qbase + u2s) * H2 + u2n] = h2T[u2n * 8 + u2s];
}

// =====================================================================
// Kernel 3: ALL heads in one launch (unchanged)
// =====================================================================
__global__ __launch_bounds__(128) void heads_kernel(
    const float* __restrict__ W1h, const float* __restrict__ b1h,
    const float* __restrict__ g1h, const float* __restrict__ be1,
    const float* __restrict__ m1h, const float* __restrict__ v1h,
    const float* __restrict__ W2h, const float* __restrict__ b2h,
    const float* __restrict__ g2h, const float* __restrict__ be2,
    const float* __restrict__ m2h, const float* __restrict__ v2h,
    const float* __restrict__ W3h, const float* __restrict__ b3h,
    const float* __restrict__ g3h, const float* __restrict__ be3,
    const float* __restrict__ m3h, const float* __restrict__ v3h,
    float* __restrict__ out)
{
    __shared__ float x[128];
    const int row = blockIdx.x;
    const int tid = threadIdx.x;

    const float *W, *b, *g, *beta, *m, *v;
    int bidx;
    if (row < 200)      { W = W1h; b = b1h; g = g1h; beta = be1; m = m1h; v = v1h; bidx = row / 25; }
    else if (row < 400) { W = W2h; b = b2h; g = g2h; beta = be2; m = m2h; v = v2h; bidx = (row - 200) / 25; }
    else                { W = W3h; b = b3h; g = g3h; beta = be3; m = m3h; v = v3h; bidx = (row - 400) / 64; }

    if (tid < 64) x[tid] = g_enc[row * H2 + tid];
    else          x[tid] = g_enc[(912 + bidx) * H2 + (tid - 64)];
    __syncthreads();

    if (tid < 32) {
        float acc = b[tid];
        #pragma unroll 8
        for (int k = 0; k < 128; k++) acc = fmaf(x[k], W[k * 32 + tid], acc);
        float y = fmaxf(acc, 0.0f);
        out[row * 32 + tid] = g[tid] * (y - m[tid]) * rsqrtf(v[tid] + 1e-3f) + beta[tid];
    }
}

// =====================================================================
extern "C" void kernel_launch(void* const* d_in, const int* in_sizes, int n_in,
                              void* d_out, int out_size)
{
    (void)in_sizes; (void)n_in; (void)out_size;

    const float* support = (const float*)d_in[0];
    const float* query   = (const float*)d_in[1];
    const float* unlabel = (const float*)d_in[2];
    const float* model   = (const float*)d_in[3];
    const float* W1 = (const float*)d_in[4];
    const float* U1 = (const float*)d_in[5];
    const float* b1 = (const float*)d_in[6];
    const float* W2 = (const float*)d_in[7];
    const float* U2 = (const float*)d_in[8];
    const float* b2 = (const float*)d_in[9];
    float* out = (float*)d_out;

    cudaFuncSetAttribute(gemm1_kernel,
                         cudaFuncAttributeMaxDynamicSharedMemorySize,
                         GEMM_SMEM_BYTES);
    dim3 ggrid(G1 / BN, MROWS / BM);   // (4, 920)
    gemm1_kernel<<<ggrid, 256, GEMM_SMEM_BYTES>>>(support, query, unlabel, model, W1);

    cudaFuncSetAttribute(lstm_kernel,
                         cudaFuncAttributeMaxDynamicSharedMemorySize,
                         LSTM_SMEM_BYTES);
    lstm_kernel<<<NSEQ / SEQ_PER_BLOCK, LSTM_THREADS, LSTM_SMEM_BYTES>>>(
        U1, b1, W2, U2, b2);

    heads_kernel<<<912, 128>>>(
        (const float*)d_in[10], (const float*)d_in[11], (const float*)d_in[12],
        (const float*)d_in[13], (const float*)d_in[14], (const float*)d_in[15],
        (const float*)d_in[16], (const float*)d_in[17], (const float*)d_in[18],
        (const float*)d_in[19], (const float*)d_in[20], (const float*)d_in[21],
        (const float*)d_in[22], (const float*)d_in[23], (const float*)d_in[24],
        (const float*)d_in[25], (const float*)d_in[26], (const float*)d_in[27],
        out);
}

// round 15
// speedup vs baseline: 2.0128x; 1.4666x over previous
#include <cuda_runtime.h>
#include <cuda_fp16.h>
#include <cuda_bf16.h>
#include <mma.h>
#include <cstdint>

using namespace nvcuda;

// ---------------- problem constants ----------------
#define T_LEN   128
#define E_DIM   768
#define H1      128
#define H2      64
#define G1      512   // 4*H1
#define G2      256   // 4*H2
#define NSEQ    920
#define MROWS   (NSEQ * T_LEN)   // 117760
#define SEQ_PER_BLOCK 8
#define LSTM_THREADS  512

#define ROW_SUP_END 25600
#define ROW_QRY_END 51200
#define ROW_UNL_END 116736

// ---------------- scratch ----------------
__device__ float  g_xw1[(long)MROWS * G1];    // 241 MB: LSTM1 input projections
__device__ __half g_xh[(long)MROWS * E_DIM];  // 181 MB: X in fp16
__device__ __half g_w1h[E_DIM * G1];          // W1 in fp16
__device__ float  g_enc[NSEQ * H2];

// ---------------- helpers ----------------
typedef unsigned long long u64t;

__device__ __forceinline__ float tanh_ap(float x) {
    float y; asm("tanh.approx.f32 %0, %1;" : "=f"(y) : "f"(x)); return y;
}
__device__ __forceinline__ float fsig(float x) {
    return fmaf(tanh_ap(0.5f * x), 0.5f, 0.5f);
}
__device__ __forceinline__ u64t ffma2p(u64t a, u64t b, u64t c) {
    u64t d;
    asm("fma.rn.f32x2 %0, %1, %2, %3;" : "=l"(d) : "l"(a), "l"(b), "l"(c));
    return d;
}
__device__ __forceinline__ u64t pack2(float x, float y) {
    u64t d; asm("mov.b64 %0, {%1, %2};" : "=l"(d) : "f"(x), "f"(y)); return d;
}
__device__ __forceinline__ void unpack2(u64t v, float& x, float& y) {
    asm("mov.b64 {%0, %1}, %2;" : "=f"(x), "=f"(y) : "l"(v));
}
__device__ __forceinline__ void cp16(void* smemDst, const void* gmemSrc) {
    unsigned sa = (unsigned)__cvta_generic_to_shared(smemDst);
    asm volatile("cp.async.cg.shared.global [%0], [%1], 16;\n" :: "r"(sa), "l"(gmemSrc));
}
#define CP_COMMIT() asm volatile("cp.async.commit_group;\n" ::)

// =====================================================================
// Kernel 0a: convert X (4 segments) -> g_xh fp16.  8 elems/thread.
// 11,304,960 chunks = 44160 blocks x 256 threads.
// =====================================================================
__global__ __launch_bounds__(256) void convert_x(
    const float* __restrict__ support,
    const float* __restrict__ query,
    const float* __restrict__ unlabel,
    const float* __restrict__ model)
{
    const long idx = (long)blockIdx.x * 256 + threadIdx.x;   // chunk of 8
    const long row = idx / 96;            // 96 chunks per row (768/8)
    const int  off = (int)(idx % 96) * 8;

    const float* A;
    long ar;
    if (row < ROW_SUP_END)      { A = support; ar = row; }
    else if (row < ROW_QRY_END) { A = query;   ar = row - ROW_SUP_END; }
    else if (row < ROW_UNL_END) { A = unlabel; ar = row - ROW_QRY_END; }
    else                        { A = model;   ar = row - ROW_UNL_END; }

    const float4* src = (const float4*)(A + ar * E_DIM + off);
    float4 v0 = src[0], v1 = src[1];
    __half2 h0 = __floats2half2_rn(v0.x, v0.y);
    __half2 h1 = __floats2half2_rn(v0.z, v0.w);
    __half2 h2 = __floats2half2_rn(v1.x, v1.y);
    __half2 h3 = __floats2half2_rn(v1.z, v1.w);
    uint4 o;
    o.x = *(unsigned*)&h0; o.y = *(unsigned*)&h1;
    o.z = *(unsigned*)&h2; o.w = *(unsigned*)&h3;
    *(uint4*)&g_xh[idx * 8] = o;
}

// Kernel 0b: convert W1 -> g_w1h fp16. 49152 chunks = 192 blocks.
__global__ __launch_bounds__(256) void convert_w(const float* __restrict__ W1)
{
    const long idx = (long)blockIdx.x * 256 + threadIdx.x;
    const float4* src = (const float4*)(W1 + idx * 8);
    float4 v0 = src[0], v1 = src[1];
    __half2 h0 = __floats2half2_rn(v0.x, v0.y);
    __half2 h1 = __floats2half2_rn(v0.z, v0.w);
    __half2 h2 = __floats2half2_rn(v1.x, v1.y);
    __half2 h3 = __floats2half2_rn(v1.z, v1.w);
    uint4 o;
    o.x = *(unsigned*)&h0; o.y = *(unsigned*)&h1;
    o.z = *(unsigned*)&h2; o.w = *(unsigned*)&h3;
    *(uint4*)&g_w1h[idx * 8] = o;
}

// =====================================================================
// Kernel 1: xw1 = Xh @ W1h, fp16 WMMA 16x16x16, fp32 accum.
// CTA tile 128x128, BK=32, 3-stage cp.async, single sync per K-tile.
// 256 threads = 8 warps (4M x 2N), warp tile 32x64.
// =====================================================================
#define BM 128
#define BN 128
#define BK 32
#define ASTRIDE_H 40    // halves (32 + 8 pad = 80 B, 16B-aligned rows)
#define BSTRIDE_H 136   // halves (128 + 8 pad = 272 B)
#define STAGE_HALVES (BM*ASTRIDE_H + BK*BSTRIDE_H)        // 5120+4352 = 9472
#define GEMM_SMEM_BYTES (3 * STAGE_HALVES * 2)            // 56832

__global__ __launch_bounds__(256, 2) void gemm1_kernel()
{
    extern __shared__ __half hsm[];

    const int bn = blockIdx.x;             // 0..3
    const int bm = blockIdx.y;             // 0..919
    const long row0 = (long)bm * BM;
    const __half* Abase = g_xh + row0 * E_DIM;

    const int tid  = threadIdx.x;
    const int warp = tid >> 5;
    const int wm   = warp & 3;    // 32-row slice
    const int wn   = warp >> 2;   // 64-col slice

    wmma::fragment<wmma::accumulator, 16, 16, 16, float> cf[2][4];
    #pragma unroll
    for (int i = 0; i < 2; i++)
        #pragma unroll
        for (int jj = 0; jj < 4; jj++)
            wmma::fill_fragment(cf[i][jj], 0.0f);

    auto load_stage = [&](int st, int k0) {
        __half* Ad = hsm + st * STAGE_HALVES;
        __half* Bd = Ad + BM * ASTRIDE_H;
        #pragma unroll
        for (int i = 0; i < 2; i++) {              // A: 512 chunks of 8 halves
            int idx = tid + i * 256;
            int r = idx >> 2, c = (idx & 3) * 8;
            cp16(&Ad[r * ASTRIDE_H + c], Abase + (long)r * E_DIM + k0 + c);
        }
        #pragma unroll
        for (int i = 0; i < 2; i++) {              // B: 512 chunks of 8 halves
            int idx = tid + i * 256;
            int r = idx >> 4, c = (idx & 15) * 8;
            cp16(&Bd[r * BSTRIDE_H + c], g_w1h + (long)(k0 + r) * G1 + bn * BN + c);
        }
        CP_COMMIT();
    };

    load_stage(0, 0);
    load_stage(1, BK);

    const int NKT = E_DIM / BK;   // 24
    int st = 0;
    for (int kt = 0; kt < NKT; kt++) {
        if (kt < NKT - 1) asm volatile("cp.async.wait_group 1;\n" ::);
        else              asm volatile("cp.async.wait_group 0;\n" ::);
        __syncthreads();

        if (kt + 2 < NKT) {
            int st2 = st + 2; if (st2 >= 3) st2 -= 3;
            load_stage(st2, (kt + 2) * BK);
        }

        const __half* Ac = hsm + st * STAGE_HALVES;
        const __half* Bc = Ac + BM * ASTRIDE_H;
        #pragma unroll
        for (int kk = 0; kk < 2; kk++) {           // two k=16 steps
            wmma::fragment<wmma::matrix_a, 16, 16, 16, __half, wmma::row_major> af[2];
            #pragma unroll
            for (int i = 0; i < 2; i++)
                wmma::load_matrix_sync(af[i], &Ac[(wm * 32 + i * 16) * ASTRIDE_H + kk * 16], ASTRIDE_H);
            #pragma unroll
            for (int jj = 0; jj < 4; jj++) {
                wmma::fragment<wmma::matrix_b, 16, 16, 16, __half, wmma::row_major> bf;
                wmma::load_matrix_sync(bf, &Bc[(kk * 16) * BSTRIDE_H + wn * 64 + jj * 16], BSTRIDE_H);
                #pragma unroll
                for (int i = 0; i < 2; i++)
                    wmma::mma_sync(cf[i][jj], af[i], bf, cf[i][jj]);
            }
        }
        if (++st >= 3) st -= 3;
    }

    #pragma unroll
    for (int i = 0; i < 2; i++)
        #pragma unroll
        for (int jj = 0; jj < 4; jj++) {
            float* dst = &g_xw1[(row0 + wm * 32 + i * 16) * (long)G1 + bn * BN + wn * 64 + jj * 16];
            wmma::store_matrix_sync(dst, cf[i][jj], G1, wmma::mem_row_major);
        }
}

// =====================================================================
// Kernel 2: fused LSTM1+LSTM2 (unchanged from R14 best)
// =====================================================================
#define LSTM_SMEM_FLOATS 56832
#define LSTM_SMEM_BYTES  (LSTM_SMEM_FLOATS * 4)

__global__ __launch_bounds__(LSTM_THREADS, 1) void lstm_kernel(
    const float* __restrict__ U1,
    const float* __restrict__ b1,
    const float* __restrict__ W2,
    const float* __restrict__ U2,
    const float* __restrict__ b2)
{
    extern __shared__ float sm[];
    float* sW2   = sm;
    float* sU2   = sm + 32768;
    float* zbufA = sm + 49152;
    float* zbufB = sm + 53248;
    float* h1T   = sm + 55296;
    float* h2T   = sm + 56320;

    const int tid = threadIdx.x;
    const long qbase = (long)blockIdx.x * SEQ_PER_BLOCK;

    {
        const float4* s4 = (const float4*)W2;
        float4* d4 = (float4*)sW2;
        for (int i = tid; i < (H1 * G2) / 4; i += LSTM_THREADS) d4[i] = s4[i];
        s4 = (const float4*)U2; d4 = (float4*)sU2;
        for (int i = tid; i < (H2 * G2) / 4; i += LSTM_THREADS) d4[i] = s4[i];
        if (tid < 64 * 8) h2T[tid] = 0.0f;
    }

    float c1a = 0.0f, c1b = 0.0f, c2 = 0.0f;

    const int j  = tid;
    const int j2 = tid & 255;
    const int s0 = (tid >> 8) * 4;

    const int p0s = tid >> 7, p0n = tid & 127;
    const int p1s = 4 + (tid >> 7), p1n = tid & 127;
    const int u2s = tid >> 6, u2n = tid & 63;

    const float* xp0 = g_xw1 + (qbase * T_LEN) * (long)G1 + j;
    const float* U1j = U1 + j;
    const float  bb  = b1[j];
    const float  b2v = b2[j2];
    const u64t   b2p = pack2(b2v, b2v);

    // pin U1[k=0..63][j] in registers
    float u1r[64];
    #pragma unroll
    for (int i = 0; i < 64; i++) u1r[i] = U1j[i * G1];

    __syncthreads();

    // prologue: z1(0) = xw(0) + b1
    {
        #pragma unroll
        for (int s = 0; s < 8; s++)
            zbufA[s * G1 + j] = xp0[(long)s * T_LEN * G1] + bb;
    }
    __syncthreads();
    {
        const float* zb = &zbufA[p0s * G1];
        float zi = zb[p0n], zf = zb[128 + p0n], zg = zb[256 + p0n], zo = zb[384 + p0n];
        c1a = fsig(zf) * c1a + fsig(zi) * tanh_ap(zg);
        h1T[p0n * 8 + p0s] = fsig(zo) * tanh_ap(c1a);
    }
    {
        const float* zb = &zbufA[p1s * G1];
        float zi = zb[p1n], zf = zb[128 + p1n], zg = zb[256 + p1n], zo = zb[384 + p1n];
        c1b = fsig(zf) * c1b + fsig(zi) * tanh_ap(zg);
        h1T[p1n * 8 + p1s] = fsig(zo) * tanh_ap(c1b);
    }
    __syncthreads();

    for (int t = 0; t < T_LEN; t++) {
        const bool notlast = (t < T_LEN - 1);

        float xv[8];
        if (notlast) {
            const float* xp = xp0 + (long)(t + 1) * G1;
            #pragma unroll
            for (int s = 0; s < 8; s++) xv[s] = xp[(long)s * T_LEN * G1];
        }

        // matvec B: z2(t)
        u64t a2a = b2p, a2b = b2p;
        #pragma unroll 8
        for (int k = 0; k < H1; k++) {
            ulonglong2 hv = *(const ulonglong2*)&h1T[k * 8 + s0];
            float wv = sW2[k * G2 + j2];
            u64t ww = pack2(wv, wv);
            a2a = ffma2p(hv.x, ww, a2a);
            a2b = ffma2p(hv.y, ww, a2b);
        }
        #pragma unroll 8
        for (int k = 0; k < H2; k++) {
            ulonglong2 hv = *(const ulonglong2*)&h2T[k * 8 + s0];
            float uv = sU2[k * G2 + j2];
            u64t uu = pack2(uv, uv);
            a2a = ffma2p(hv.x, uu, a2a);
            a2b = ffma2p(hv.y, uu, a2b);
        }

        // matvec A: z1(t+1)
        u64t a01 = 0ull, a23 = 0ull, a45 = 0ull, a67 = 0ull;
        if (notlast) {
            #pragma unroll
            for (int i = 0; i < 64; i++) {
                ulonglong2 hA = *(const ulonglong2*)&h1T[i * 8];
                ulonglong2 hB = *(const ulonglong2*)&h1T[i * 8 + 4];
                u64t uu = pack2(u1r[i], u1r[i]);
                a01 = ffma2p(hA.x, uu, a01);
                a23 = ffma2p(hA.y, uu, a23);
                a45 = ffma2p(hB.x, uu, a45);
                a67 = ffma2p(hB.y, uu, a67);
            }
            #pragma unroll 1
            for (int kb = 64; kb < H1; kb += 16) {
                float u[16];
                #pragma unroll
                for (int i = 0; i < 16; i++) u[i] = U1j[(kb + i) * G1];
                #pragma unroll
                for (int i = 0; i < 16; i++) {
                    ulonglong2 hA = *(const ulonglong2*)&h1T[(kb + i) * 8];
                    ulonglong2 hB = *(const ulonglong2*)&h1T[(kb + i) * 8 + 4];
                    u64t uu = pack2(u[i], u[i]);
                    a01 = ffma2p(hA.x, uu, a01);
                    a23 = ffma2p(hA.y, uu, a23);
                    a45 = ffma2p(hB.x, uu, a45);
                    a67 = ffma2p(hB.y, uu, a67);
                }
            }
        }

        // stores
        {
            float y0, y1, y2, y3;
            unpack2(a2a, y0, y1); unpack2(a2b, y2, y3);
            zbufB[(s0 + 0) * G2 + j2] = y0;
            zbufB[(s0 + 1) * G2 + j2] = y1;
            zbufB[(s0 + 2) * G2 + j2] = y2;
            zbufB[(s0 + 3) * G2 + j2] = y3;
        }
        if (notlast) {
            float z0, z1, z2, z3, z4, z5, z6, z7;
            unpack2(a01, z0, z1); unpack2(a23, z2, z3);
            unpack2(a45, z4, z5); unpack2(a67, z6, z7);
            zbufA[0 * G1 + j] = z0 + xv[0] + bb;
            zbufA[1 * G1 + j] = z1 + xv[1] + bb;
            zbufA[2 * G1 + j] = z2 + xv[2] + bb;
            zbufA[3 * G1 + j] = z3 + xv[3] + bb;
            zbufA[4 * G1 + j] = z4 + xv[4] + bb;
            zbufA[5 * G1 + j] = z5 + xv[5] + bb;
            zbufA[6 * G1 + j] = z6 + xv[6] + bb;
            zbufA[7 * G1 + j] = z7 + xv[7] + bb;
        }
        __syncthreads();

        // update2(t)
        {
            const float* zb = &zbufB[u2s * G2];
            float zi = zb[u2n], zf = zb[64 + u2n], zg = zb[128 + u2n], zo = zb[192 + u2n];
            c2 = fsig(zf) * c2 + fsig(zi) * tanh_ap(zg);
            h2T[u2n * 8 + u2s] = fsig(zo) * tanh_ap(c2);
        }
        // update1(t+1)
        if (notlast) {
            {
                const float* zb = &zbufA[p0s * G1];
                float zi = zb[p0n], zf = zb[128 + p0n], zg = zb[256 + p0n], zo = zb[384 + p0n];
                c1a = fsig(zf) * c1a + fsig(zi) * tanh_ap(zg);
                h1T[p0n * 8 + p0s] = fsig(zo) * tanh_ap(c1a);
            }
            {
                const float* zb = &zbufA[p1s * G1];
                float zi = zb[p1n], zf = zb[128 + p1n], zg = zb[256 + p1n], zo = zb[384 + p1n];
                c1b = fsig(zf) * c1b + fsig(zi) * tanh_ap(zg);
                h1T[p1n * 8 + p1s] = fsig(zo) * tanh_ap(c1b);
            }
        }
        __syncthreads();
    }

    g_enc[(qbase + u2s) * H2 + u2n] = h2T[u2n * 8 + u2s];
}

// =====================================================================
// Kernel 3: ALL heads in one launch (unchanged)
// =====================================================================
__global__ __launch_bounds__(128) void heads_kernel(
    const float* __restrict__ W1h_, const float* __restrict__ b1h,
    const float* __restrict__ g1h, const float* __restrict__ be1,
    const float* __restrict__ m1h, const float* __restrict__ v1h,
    const float* __restrict__ W2h, const float* __restrict__ b2h,
    const float* __restrict__ g2h, const float* __restrict__ be2,
    const float* __restrict__ m2h, const float* __restrict__ v2h,
    const float* __restrict__ W3h, const float* __restrict__ b3h,
    const float* __restrict__ g3h, const float* __restrict__ be3,
    const float* __restrict__ m3h, const float* __restrict__ v3h,
    float* __restrict__ out)
{
    __shared__ float x[128];
    const int row = blockIdx.x;
    const int tid = threadIdx.x;

    const float *W, *b, *g, *beta, *m, *v;
    int bidx;
    if (row < 200)      { W = W1h_; b = b1h; g = g1h; beta = be1; m = m1h; v = v1h; bidx = row / 25; }
    else if (row < 400) { W = W2h; b = b2h; g = g2h; beta = be2; m = m2h; v = v2h; bidx = (row - 200) / 25; }
    else                { W = W3h; b = b3h; g = g3h; beta = be3; m = m3h; v = v3h; bidx = (row - 400) / 64; }

    if (tid < 64) x[tid] = g_enc[row * H2 + tid];
    else          x[tid] = g_enc[(912 + bidx) * H2 + (tid - 64)];
    __syncthreads();

    if (tid < 32) {
        float acc = b[tid];
        #pragma unroll 8
        for (int k = 0; k < 128; k++) acc = fmaf(x[k], W[k * 32 + tid], acc);
        float y = fmaxf(acc, 0.0f);
        out[row * 32 + tid] = g[tid] * (y - m[tid]) * rsqrtf(v[tid] + 1e-3f) + beta[tid];
    }
}

// =====================================================================
extern "C" void kernel_launch(void* const* d_in, const int* in_sizes, int n_in,
                              void* d_out, int out_size)
{
    (void)in_sizes; (void)n_in; (void)out_size;

    const float* support = (const float*)d_in[0];
    const float* query   = (const float*)d_in[1];
    const float* unlabel = (const float*)d_in[2];
    const float* model   = (const float*)d_in[3];
    const float* W1 = (const float*)d_in[4];
    const float* U1 = (const float*)d_in[5];
    const float* b1 = (const float*)d_in[6];
    const float* W2 = (const float*)d_in[7];
    const float* U2 = (const float*)d_in[8];
    const float* b2 = (const float*)d_in[9];
    float* out = (float*)d_out;

    // Phase 0: fp16 conversion of X and W1
    convert_x<<<44160, 256>>>(support, query, unlabel, model);
    convert_w<<<192, 256>>>(W1);

    // Phase 1: fp16 WMMA GEMM
    cudaFuncSetAttribute(gemm1_kernel,
                         cudaFuncAttributeMaxDynamicSharedMemorySize,
                         GEMM_SMEM_BYTES);
    dim3 ggrid(G1 / BN, MROWS / BM);   // (4, 920)
    gemm1_kernel<<<ggrid, 256, GEMM_SMEM_BYTES>>>();

    // Phase 2: fused LSTM
    cudaFuncSetAttribute(lstm_kernel,
                         cudaFuncAttributeMaxDynamicSharedMemorySize,
                         LSTM_SMEM_BYTES);
    lstm_kernel<<<NSEQ / SEQ_PER_BLOCK, LSTM_THREADS, LSTM_SMEM_BYTES>>>(
        U1, b1, W2, U2, b2);

    // Phase 3: heads
    heads_kernel<<<912, 128>>>(
        (const float*)d_in[10], (const float*)d_in[11], (const float*)d_in[12],
        (const float*)d_in[13], (const float*)d_in[14], (const float*)d_in[15],
        (const float*)d_in[16], (const float*)d_in[17], (const float*)d_in[18],
        (const float*)d_in[19], (const float*)d_in[20], (const float*)d_in[21],
        (const float*)d_in[22], (const float*)d_in[23], (const float*)d_in[24],
        (const float*)d_in[25], (const float*)d_in[26], (const float*)d_in[27],
        out);
}

// round 16
// speedup vs baseline: 2.6001x; 1.2918x over previous
#include <cuda_runtime.h>
#include <cuda_fp16.h>
#include <cuda_bf16.h>
#include <mma.h>
#include <cstdint>

using namespace nvcuda;

// ---------------- problem constants ----------------
#define T_LEN   128
#define E_DIM   768
#define H1      128
#define H2      64
#define G1      512   // 4*H1
#define G2      256   // 4*H2
#define NSEQ    920
#define MROWS   (NSEQ * T_LEN)   // 117760
#define SEQ_PER_BLOCK 8
#define LSTM_THREADS  512

#define ROW_SUP_END 25600
#define ROW_QRY_END 51200
#define ROW_UNL_END 116736

// ---------------- scratch ----------------
__device__ float  g_xw1[(long)MROWS * G1];    // 241 MB: LSTM1 input projections
__device__ __half g_xh[(long)MROWS * E_DIM];  // 181 MB: X in fp16
__device__ __half g_w1h[E_DIM * G1];          // W1 in fp16
__device__ __half g_u1h[H1 * G1];             // U1 in fp16 (k-major, as given)
__device__ __half g_wch[(H1 + H2) * G2];      // [W2;U2] in fp16 (192 x 256)
__device__ float  g_enc[NSEQ * H2];

// ---------------- helpers ----------------
__device__ __forceinline__ float tanh_ap(float x) {
    float y; asm("tanh.approx.f32 %0, %1;" : "=f"(y) : "f"(x)); return y;
}
__device__ __forceinline__ float fsig(float x) {
    return fmaf(tanh_ap(0.5f * x), 0.5f, 0.5f);
}
__device__ __forceinline__ void cp16(void* smemDst, const void* gmemSrc) {
    unsigned sa = (unsigned)__cvta_generic_to_shared(smemDst);
    asm volatile("cp.async.cg.shared.global [%0], [%1], 16;\n" :: "r"(sa), "l"(gmemSrc));
}
#define CP_COMMIT() asm volatile("cp.async.commit_group;\n" ::)

// =====================================================================
// Kernel 0a: convert X (4 segments) -> g_xh fp16. 8 elems/thread.
// =====================================================================
__global__ __launch_bounds__(256) void convert_x(
    const float* __restrict__ support,
    const float* __restrict__ query,
    const float* __restrict__ unlabel,
    const float* __restrict__ model)
{
    const long idx = (long)blockIdx.x * 256 + threadIdx.x;   // chunk of 8
    const long row = idx / 96;
    const int  off = (int)(idx % 96) * 8;

    const float* A;
    long ar;
    if (row < ROW_SUP_END)      { A = support; ar = row; }
    else if (row < ROW_QRY_END) { A = query;   ar = row - ROW_SUP_END; }
    else if (row < ROW_UNL_END) { A = unlabel; ar = row - ROW_QRY_END; }
    else                        { A = model;   ar = row - ROW_UNL_END; }

    const float4* src = (const float4*)(A + ar * E_DIM + off);
    float4 v0 = src[0], v1 = src[1];
    __half2 h0 = __floats2half2_rn(v0.x, v0.y);
    __half2 h1 = __floats2half2_rn(v0.z, v0.w);
    __half2 h2 = __floats2half2_rn(v1.x, v1.y);
    __half2 h3 = __floats2half2_rn(v1.z, v1.w);
    uint4 o;
    o.x = *(unsigned*)&h0; o.y = *(unsigned*)&h1;
    o.z = *(unsigned*)&h2; o.w = *(unsigned*)&h3;
    *(uint4*)&g_xh[idx * 8] = o;
}

// Kernel 0b: convert W1 -> g_w1h fp16. (49152 chunks of 8)
__global__ __launch_bounds__(256) void convert_w(const float* __restrict__ W1)
{
    const long idx = (long)blockIdx.x * 256 + threadIdx.x;
    const float4* src = (const float4*)(W1 + idx * 8);
    float4 v0 = src[0], v1 = src[1];
    __half2 h0 = __floats2half2_rn(v0.x, v0.y);
    __half2 h1 = __floats2half2_rn(v0.z, v0.w);
    __half2 h2 = __floats2half2_rn(v1.x, v1.y);
    __half2 h3 = __floats2half2_rn(v1.z, v1.w);
    uint4 o;
    o.x = *(unsigned*)&h0; o.y = *(unsigned*)&h1;
    o.z = *(unsigned*)&h2; o.w = *(unsigned*)&h3;
    *(uint4*)&g_w1h[idx * 8] = o;
}

// Kernel 0c: convert U1 -> g_u1h (65536 elems) and [W2;U2] -> g_wch (49152).
__global__ __launch_bounds__(256) void convert_rec(
    const float* __restrict__ U1,
    const float* __restrict__ W2,
    const float* __restrict__ U2)
{
    const long idx = (long)blockIdx.x * 256 + threadIdx.x;   // chunk of 8
    const long e = idx * 8;
    const float* src;
    __half* dst;
    if (e < H1 * G1) {                 // U1: 65536 elems
        src = U1 + e;       dst = g_u1h + e;
    } else {
        long e2 = e - (long)H1 * G1;   // Wc: 49152 elems
        dst = g_wch + e2;
        src = (e2 < H1 * G2) ? (W2 + e2) : (U2 + e2 - H1 * G2);
    }
    float4 v0 = *(const float4*)src, v1 = *(const float4*)(src + 4);
    __half2 h0 = __floats2half2_rn(v0.x, v0.y);
    __half2 h1 = __floats2half2_rn(v0.z, v0.w);
    __half2 h2 = __floats2half2_rn(v1.x, v1.y);
    __half2 h3 = __floats2half2_rn(v1.z, v1.w);
    uint4 o;
    o.x = *(unsigned*)&h0; o.y = *(unsigned*)&h1;
    o.z = *(unsigned*)&h2; o.w = *(unsigned*)&h3;
    *(uint4*)dst = o;
}

// =====================================================================
// Kernel 1: xw1 = Xh @ W1h, fp16 WMMA 16x16x16 (unchanged from R15)
// =====================================================================
#define BM 128
#define BN 128
#define BK 32
#define ASTRIDE_H 40
#define BSTRIDE_H 136
#define STAGE_HALVES (BM*ASTRIDE_H + BK*BSTRIDE_H)        // 9472
#define GEMM_SMEM_BYTES (3 * STAGE_HALVES * 2)            // 56832

__global__ __launch_bounds__(256, 2) void gemm1_kernel()
{
    extern __shared__ __half hsm[];

    const int bn = blockIdx.x;
    const int bm = blockIdx.y;
    const long row0 = (long)bm * BM;
    const __half* Abase = g_xh + row0 * E_DIM;

    const int tid  = threadIdx.x;
    const int warp = tid >> 5;
    const int wm   = warp & 3;
    const int wn   = warp >> 2;

    wmma::fragment<wmma::accumulator, 16, 16, 16, float> cf[2][4];
    #pragma unroll
    for (int i = 0; i < 2; i++)
        #pragma unroll
        for (int jj = 0; jj < 4; jj++)
            wmma::fill_fragment(cf[i][jj], 0.0f);

    auto load_stage = [&](int st, int k0) {
        __half* Ad = hsm + st * STAGE_HALVES;
        __half* Bd = Ad + BM * ASTRIDE_H;
        #pragma unroll
        for (int i = 0; i < 2; i++) {
            int idx = tid + i * 256;
            int r = idx >> 2, c = (idx & 3) * 8;
            cp16(&Ad[r * ASTRIDE_H + c], Abase + (long)r * E_DIM + k0 + c);
        }
        #pragma unroll
        for (int i = 0; i < 2; i++) {
            int idx = tid + i * 256;
            int r = idx >> 4, c = (idx & 15) * 8;
            cp16(&Bd[r * BSTRIDE_H + c], g_w1h + (long)(k0 + r) * G1 + bn * BN + c);
        }
        CP_COMMIT();
    };

    load_stage(0, 0);
    load_stage(1, BK);

    const int NKT = E_DIM / BK;
    int st = 0;
    for (int kt = 0; kt < NKT; kt++) {
        if (kt < NKT - 1) asm volatile("cp.async.wait_group 1;\n" ::);
        else              asm volatile("cp.async.wait_group 0;\n" ::);
        __syncthreads();

        if (kt + 2 < NKT) {
            int st2 = st + 2; if (st2 >= 3) st2 -= 3;
            load_stage(st2, (kt + 2) * BK);
        }

        const __half* Ac = hsm + st * STAGE_HALVES;
        const __half* Bc = Ac + BM * ASTRIDE_H;
        #pragma unroll
        for (int kk = 0; kk < 2; kk++) {
            wmma::fragment<wmma::matrix_a, 16, 16, 16, __half, wmma::row_major> af[2];
            #pragma unroll
            for (int i = 0; i < 2; i++)
                wmma::load_matrix_sync(af[i], &Ac[(wm * 32 + i * 16) * ASTRIDE_H + kk * 16], ASTRIDE_H);
            #pragma unroll
            for (int jj = 0; jj < 4; jj++) {
                wmma::fragment<wmma::matrix_b, 16, 16, 16, __half, wmma::row_major> bf;
                wmma::load_matrix_sync(bf, &Bc[(kk * 16) * BSTRIDE_H + wn * 64 + jj * 16], BSTRIDE_H);
                #pragma unroll
                for (int i = 0; i < 2; i++)
                    wmma::mma_sync(cf[i][jj], af[i], bf, cf[i][jj]);
            }
        }
        if (++st >= 3) st -= 3;
    }

    #pragma unroll
    for (int i = 0; i < 2; i++)
        #pragma unroll
        for (int jj = 0; jj < 4; jj++) {
            float* dst = &g_xw1[(row0 + wm * 32 + i * 16) * (long)G1 + bn * BN + wn * 64 + jj * 16];
            wmma::store_matrix_sync(dst, cf[i][jj], G1, wmma::mem_row_major);
        }
}

// =====================================================================
// Kernel 2: fused LSTM1+LSTM2 on TENSOR CORES (wmma m8n32k16 fp16).
// Per step per block (8 seqs):
//   Phase A: z1(t+1) = h1(t)[8x128] @ U1[128x512]  (U1 frags from L2)
//   Phase B: z2(t)   = [h1|h2][8x192] @ Wc[192x256] (Wc in smem, K-split 2)
//   16 warps: warp w -> A-tile n0=w*32 (8 mmas) + B-tile (w>>1), K-half (w&1).
// Update threads apply activations (fp32 cell state in registers);
// h written back as fp16 (fp32 shadow of h2 for enc output).
// smem (bytes): Wch 101376 | zA 16384 | zBp 16384 | hB 3200 | h2f 2048
// =====================================================================
#define HBLD 200   // hB row stride in halves (8 rows: [h1(0..127)|h2(128..191)|pad])
#define WLD  264   // Wch row stride in halves
#define OFF_ZA   101376
#define OFF_ZBP  117760
#define OFF_HB   134144
#define OFF_H2F  137344
#define LSTM_SMEM_BYTES 139392

__global__ __launch_bounds__(LSTM_THREADS, 1) void lstm_kernel(
    const float* __restrict__ b1,
    const float* __restrict__ b2)
{
    extern __shared__ char smx[];
    __half* Wch = (__half*)smx;
    float*  zA  = (float*)(smx + OFF_ZA);    // [8][512]
    float*  zBp = (float*)(smx + OFF_ZBP);   // [2][8][256]
    __half* hB  = (__half*)(smx + OFF_HB);   // [8][HBLD]
    float*  h2f = (float*)(smx + OFF_H2F);   // [8][64]

    const int tid  = threadIdx.x;
    const int warp = tid >> 5;
    const long qbase = (long)blockIdx.x * SEQ_PER_BLOCK;

    // load Wc into smem (192 rows x 256 halves, padded stride WLD)
    for (int i = tid; i < 192 * 32; i += LSTM_THREADS) {
        int r = i >> 5, c = (i & 31) * 8;
        *(uint4*)&Wch[r * WLD + c] = *(const uint4*)&g_wch[r * G2 + c];
    }
    // zero h2 region + shadow
    {
        int s = tid >> 6, n = tid & 63;
        hB[s * HBLD + 128 + n] = __float2half(0.0f);
        h2f[s * 64 + n] = 0.0f;
    }

    // update-thread mappings
    const int p0s = tid >> 7, p0n = tid & 127;   // update1 state A (s=0..3)
    const int p1s = p0s + 4;                     // update1 state B (s=4..7)
    const int u2s = tid >> 6, u2n = tid & 63;    // update2 (1 state)

    float c1a = 0.0f, c1b = 0.0f, c2 = 0.0f;

    const float b1i = b1[p0n], b1f = b1[128 + p0n],
                b1g = b1[256 + p0n], b1o = b1[384 + p0n];
    const float b2i = b2[u2n], b2f = b2[64 + u2n],
                b2g = b2[128 + u2n], b2o = b2[192 + u2n];

    __syncthreads();

    // ---- prologue: h1(0) from xw(0)+b1 (h1(-1)=0, c=0) ----
    {
        const float* xp = g_xw1 + ((qbase + p0s) * T_LEN) * (long)G1;
        float zi = xp[p0n] + b1i, zf = xp[128 + p0n] + b1f;
        float zg = xp[256 + p0n] + b1g, zo = xp[384 + p0n] + b1o;
        (void)zf;
        c1a = fsig(zi) * tanh_ap(zg);
        hB[p0s * HBLD + p0n] = __float2half(fsig(zo) * tanh_ap(c1a));
    }
    {
        const float* xp = g_xw1 + ((qbase + p1s) * T_LEN) * (long)G1;
        float zi = xp[p0n] + b1i, zf = xp[128 + p0n] + b1f;
        float zg = xp[256 + p0n] + b1g, zo = xp[384 + p0n] + b1o;
        (void)zf;
        c1b = fsig(zi) * tanh_ap(zg);
        hB[p1s * HBLD + p0n] = __float2half(fsig(zo) * tanh_ap(c1b));
    }
    __syncthreads();

    const int btile = warp >> 1;     // Phase B N-tile (0..7)
    const int kh    = warp & 1;      // Phase B K-half

    for (int t = 0; t < T_LEN; t++) {
        const bool notlast = (t < T_LEN - 1);

        // ================= MMA phase =================
        // Phase A: z1(t+1) raw, N-tile = warp*32
        {
            wmma::fragment<wmma::accumulator, 8, 32, 16, float> acc;
            wmma::fill_fragment(acc, 0.0f);
            #pragma unroll
            for (int ks = 0; ks < 8; ks++) {
                wmma::fragment<wmma::matrix_a, 8, 32, 16, __half, wmma::row_major> af;
                wmma::load_matrix_sync(af, hB + ks * 16, HBLD);
                wmma::fragment<wmma::matrix_b, 8, 32, 16, __half, wmma::row_major> bf;
                wmma::load_matrix_sync(bf, g_u1h + (ks * 16) * G1 + warp * 32, G1);
                wmma::mma_sync(acc, af, bf, acc);
            }
            wmma::store_matrix_sync(zA + warp * 32, acc, G1, wmma::mem_row_major);
        }
        // Phase B: z2(t) K-half partial, N-tile = btile*32
        {
            wmma::fragment<wmma::accumulator, 8, 32, 16, float> acc;
            wmma::fill_fragment(acc, 0.0f);
            #pragma unroll
            for (int ks = 0; ks < 6; ks++) {
                int k0 = kh * 96 + ks * 16;
                wmma::fragment<wmma::matrix_a, 8, 32, 16, __half, wmma::row_major> af;
                wmma::load_matrix_sync(af, hB + k0, HBLD);
                wmma::fragment<wmma::matrix_b, 8, 32, 16, __half, wmma::row_major> bf;
                wmma::load_matrix_sync(bf, Wch + k0 * WLD + btile * 32, WLD);
                wmma::mma_sync(acc, af, bf, acc);
            }
            wmma::store_matrix_sync(zBp + kh * (8 * G2) + btile * 32, acc, G2,
                                    wmma::mem_row_major);
        }
        __syncthreads();

        // ================= update phase =================
        // update2(t): h2(t), c2   (1 state/thread)
        {
            const float* z0 = zBp + u2s * G2 + u2n;
            const float* z1 = z0 + 8 * G2;
            float zi = z0[0]   + z1[0]   + b2i;
            float zf = z0[64]  + z1[64]  + b2f;
            float zg = z0[128] + z1[128] + b2g;
            float zo = z0[192] + z1[192] + b2o;
            c2 = fsig(zf) * c2 + fsig(zi) * tanh_ap(zg);
            float h = fsig(zo) * tanh_ap(c2);
            hB[u2s * HBLD + 128 + u2n] = __float2half(h);
            h2f[u2s * 64 + u2n] = h;
        }
        // update1(t+1): h1(t+1), c1   (2 states/thread)
        if (notlast) {
            {
                const float* xp = g_xw1 + ((qbase + p0s) * T_LEN + t + 1) * (long)G1;
                const float* za = zA + p0s * G1;
                float zi = za[p0n]       + xp[p0n]       + b1i;
                float zf = za[128 + p0n] + xp[128 + p0n] + b1f;
                float zg = za[256 + p0n] + xp[256 + p0n] + b1g;
                float zo = za[384 + p0n] + xp[384 + p0n] + b1o;
                c1a = fsig(zf) * c1a + fsig(zi) * tanh_ap(zg);
                hB[p0s * HBLD + p0n] = __float2half(fsig(zo) * tanh_ap(c1a));
            }
            {
                const float* xp = g_xw1 + ((qbase + p1s) * T_LEN + t + 1) * (long)G1;
                const float* za = zA + p1s * G1;
                float zi = za[p0n]       + xp[p0n]       + b1i;
                float zf = za[128 + p0n] + xp[128 + p0n] + b1f;
                float zg = za[256 + p0n] + xp[256 + p0n] + b1g;
                float zo = za[384 + p0n] + xp[384 + p0n] + b1o;
                c1b = fsig(zf) * c1b + fsig(zi) * tanh_ap(zg);
                hB[p1s * HBLD + p0n] = __float2half(fsig(zo) * tanh_ap(c1b));
            }
        }
        __syncthreads();
    }

    // output encodings (fp32 shadow of h2)
    g_enc[(qbase + u2s) * H2 + u2n] = h2f[u2s * 64 + u2n];
}

// =====================================================================
// Kernel 3: ALL heads in one launch (unchanged)
// =====================================================================
__global__ __launch_bounds__(128) void heads_kernel(
    const float* __restrict__ W1h_, const float* __restrict__ b1h,
    const float* __restrict__ g1h, const float* __restrict__ be1,
    const float* __restrict__ m1h, const float* __restrict__ v1h,
    const float* __restrict__ W2h, const float* __restrict__ b2h,
    const float* __restrict__ g2h, const float* __restrict__ be2,
    const float* __restrict__ m2h, const float* __restrict__ v2h,
    const float* __restrict__ W3h, const float* __restrict__ b3h,
    const float* __restrict__ g3h, const float* __restrict__ be3,
    const float* __restrict__ m3h, const float* __restrict__ v3h,
    float* __restrict__ out)
{
    __shared__ float x[128];
    const int row = blockIdx.x;
    const int tid = threadIdx.x;

    const float *W, *b, *g, *beta, *m, *v;
    int bidx;
    if (row < 200)      { W = W1h_; b = b1h; g = g1h; beta = be1; m = m1h; v = v1h; bidx = row / 25; }
    else if (row < 400) { W = W2h; b = b2h; g = g2h; beta = be2; m = m2h; v = v2h; bidx = (row - 200) / 25; }
    else                { W = W3h; b = b3h; g = g3h; beta = be3; m = m3h; v = v3h; bidx = (row - 400) / 64; }

    if (tid < 64) x[tid] = g_enc[row * H2 + tid];
    else          x[tid] = g_enc[(912 + bidx) * H2 + (tid - 64)];
    __syncthreads();

    if (tid < 32) {
        float acc = b[tid];
        #pragma unroll 8
        for (int k = 0; k < 128; k++) acc = fmaf(x[k], W[k * 32 + tid], acc);
        float y = fmaxf(acc, 0.0f);
        out[row * 32 + tid] = g[tid] * (y - m[tid]) * rsqrtf(v[tid] + 1e-3f) + beta[tid];
    }
}

// =====================================================================
extern "C" void kernel_launch(void* const* d_in, const int* in_sizes, int n_in,
                              void* d_out, int out_size)
{
    (void)in_sizes; (void)n_in; (void)out_size;

    const float* support = (const float*)d_in[0];
    const float* query   = (const float*)d_in[1];
    const float* unlabel = (const float*)d_in[2];
    const float* model   = (const float*)d_in[3];
    const float* W1 = (const float*)d_in[4];
    const float* U1 = (const float*)d_in[5];
    const float* b1 = (const float*)d_in[6];
    const float* W2 = (const float*)d_in[7];
    const float* U2 = (const float*)d_in[8];
    const float* b2 = (const float*)d_in[9];
    float* out = (float*)d_out;

    // Phase 0: fp16 conversions
    convert_x<<<44160, 256>>>(support, query, unlabel, model);
    convert_w<<<192, 256>>>(W1);
    convert_rec<<<56, 256>>>(U1, W2, U2);   // (65536+49152)/8 = 14336 thr

    // Phase 1: fp16 WMMA GEMM
    cudaFuncSetAttribute(gemm1_kernel,
                         cudaFuncAttributeMaxDynamicSharedMemorySize,
                         GEMM_SMEM_BYTES);
    dim3 ggrid(G1 / BN, MROWS / BM);   // (4, 920)
    gemm1_kernel<<<ggrid, 256, GEMM_SMEM_BYTES>>>();

    // Phase 2: tensor-core LSTM
    cudaFuncSetAttribute(lstm_kernel,
                         cudaFuncAttributeMaxDynamicSharedMemorySize,
                         LSTM_SMEM_BYTES);
    lstm_kernel<<<NSEQ / SEQ_PER_BLOCK, LSTM_THREADS, LSTM_SMEM_BYTES>>>(b1, b2);

    // Phase 3: heads
    heads_kernel<<<912, 128>>>(
        (const float*)d_in[10], (const float*)d_in[11], (const float*)d_in[12],
        (const float*)d_in[13], (const float*)d_in[14], (const float*)d_in[15],
        (const float*)d_in[16], (const float*)d_in[17], (const float*)d_in[18],
        (const float*)d_in[19], (const float*)d_in[20], (const float*)d_in[21],
        (const float*)d_in[22], (const float*)d_in[23], (const float*)d_in[24],
        (const float*)d_in[25], (const float*)d_in[26], (const float*)d_in[27],
        out);
}

// round 17
// speedup vs baseline: 4.9788x; 1.9149x over previous
#include <cuda_runtime.h>
#include <cuda_fp16.h>
#include <cuda_bf16.h>
#include <mma.h>
#include <cstdint>

using namespace nvcuda;

// ---------------- problem constants ----------------
#define T_LEN   128
#define E_DIM   768
#define H1      128
#define H2      64
#define G1      512   // 4*H1
#define G2      256   // 4*H2
#define NSEQ    920
#define MROWS   (NSEQ * T_LEN)   // 117760
#define SEQ_PER_BLOCK 8
#define LSTM_THREADS  512

#define ROW_SUP_END 25600
#define ROW_QRY_END 51200
#define ROW_UNL_END 116736

// ---------------- scratch ----------------
__device__ float  g_xw1[(long)MROWS * G1];    // 241 MB: LSTM1 input projections
__device__ __half g_xh[(long)MROWS * E_DIM];  // 181 MB: X in fp16
__device__ __half g_w1h[E_DIM * G1];          // W1 in fp16
__device__ __half g_u1h[H1 * G1];             // U1 in fp16 (k-major)
__device__ __half g_wch[(H1 + H2) * G2];      // [W2;U2] in fp16 (192 x 256)
__device__ float  g_enc[NSEQ * H2];

// ---------------- helpers ----------------
__device__ __forceinline__ float tanh_ap(float x) {
    float y; asm("tanh.approx.f32 %0, %1;" : "=f"(y) : "f"(x)); return y;
}
__device__ __forceinline__ float fsig(float x) {
    return fmaf(tanh_ap(0.5f * x), 0.5f, 0.5f);
}
__device__ __forceinline__ void cp16(void* smemDst, const void* gmemSrc) {
    unsigned sa = (unsigned)__cvta_generic_to_shared(smemDst);
    asm volatile("cp.async.cg.shared.global [%0], [%1], 16;\n" :: "r"(sa), "l"(gmemSrc));
}
#define CP_COMMIT() asm volatile("cp.async.commit_group;\n" ::)

// =====================================================================
// Kernel 0a: convert X (4 segments) -> g_xh fp16. 8 elems/thread.
// =====================================================================
__global__ __launch_bounds__(256) void convert_x(
    const float* __restrict__ support,
    const float* __restrict__ query,
    const float* __restrict__ unlabel,
    const float* __restrict__ model)
{
    const long idx = (long)blockIdx.x * 256 + threadIdx.x;   // chunk of 8
    const long row = idx / 96;
    const int  off = (int)(idx % 96) * 8;

    const float* A;
    long ar;
    if (row < ROW_SUP_END)      { A = support; ar = row; }
    else if (row < ROW_QRY_END) { A = query;   ar = row - ROW_SUP_END; }
    else if (row < ROW_UNL_END) { A = unlabel; ar = row - ROW_QRY_END; }
    else                        { A = model;   ar = row - ROW_UNL_END; }

    const float4* src = (const float4*)(A + ar * E_DIM + off);
    float4 v0 = src[0], v1 = src[1];
    __half2 h0 = __floats2half2_rn(v0.x, v0.y);
    __half2 h1 = __floats2half2_rn(v0.z, v0.w);
    __half2 h2 = __floats2half2_rn(v1.x, v1.y);
    __half2 h3 = __floats2half2_rn(v1.z, v1.w);
    uint4 o;
    o.x = *(unsigned*)&h0; o.y = *(unsigned*)&h1;
    o.z = *(unsigned*)&h2; o.w = *(unsigned*)&h3;
    *(uint4*)&g_xh[idx * 8] = o;
}

// Kernel 0b: convert W1 -> g_w1h fp16.
__global__ __launch_bounds__(256) void convert_w(const float* __restrict__ W1)
{
    const long idx = (long)blockIdx.x * 256 + threadIdx.x;
    const float4* src = (const float4*)(W1 + idx * 8);
    float4 v0 = src[0], v1 = src[1];
    __half2 h0 = __floats2half2_rn(v0.x, v0.y);
    __half2 h1 = __floats2half2_rn(v0.z, v0.w);
    __half2 h2 = __floats2half2_rn(v1.x, v1.y);
    __half2 h3 = __floats2half2_rn(v1.z, v1.w);
    uint4 o;
    o.x = *(unsigned*)&h0; o.y = *(unsigned*)&h1;
    o.z = *(unsigned*)&h2; o.w = *(unsigned*)&h3;
    *(uint4*)&g_w1h[idx * 8] = o;
}

// Kernel 0c: convert U1 -> g_u1h and [W2;U2] -> g_wch.
__global__ __launch_bounds__(256) void convert_rec(
    const float* __restrict__ U1,
    const float* __restrict__ W2,
    const float* __restrict__ U2)
{
    const long idx = (long)blockIdx.x * 256 + threadIdx.x;
    const long e = idx * 8;
    const float* src;
    __half* dst;
    if (e < H1 * G1) {
        src = U1 + e;       dst = g_u1h + e;
    } else {
        long e2 = e - (long)H1 * G1;
        dst = g_wch + e2;
        src = (e2 < H1 * G2) ? (W2 + e2) : (U2 + e2 - H1 * G2);
    }
    float4 v0 = *(const float4*)src, v1 = *(const float4*)(src + 4);
    __half2 h0 = __floats2half2_rn(v0.x, v0.y);
    __half2 h1 = __floats2half2_rn(v0.z, v0.w);
    __half2 h2 = __floats2half2_rn(v1.x, v1.y);
    __half2 h3 = __floats2half2_rn(v1.z, v1.w);
    uint4 o;
    o.x = *(unsigned*)&h0; o.y = *(unsigned*)&h1;
    o.z = *(unsigned*)&h2; o.w = *(unsigned*)&h3;
    *(uint4*)dst = o;
}

// =====================================================================
// Kernel 1: xw1 = Xh @ W1h, fp16 WMMA 16x16x16 (unchanged from R15/R16)
// =====================================================================
#define BM 128
#define BN 128
#define BK 32
#define ASTRIDE_H 40
#define BSTRIDE_H 136
#define STAGE_HALVES (BM*ASTRIDE_H + BK*BSTRIDE_H)        // 9472
#define GEMM_SMEM_BYTES (3 * STAGE_HALVES * 2)            // 56832

__global__ __launch_bounds__(256, 2) void gemm1_kernel()
{
    extern __shared__ __half hsm[];

    const int bn = blockIdx.x;
    const int bm = blockIdx.y;
    const long row0 = (long)bm * BM;
    const __half* Abase = g_xh + row0 * E_DIM;

    const int tid  = threadIdx.x;
    const int warp = tid >> 5;
    const int wm   = warp & 3;
    const int wn   = warp >> 2;

    wmma::fragment<wmma::accumulator, 16, 16, 16, float> cf[2][4];
    #pragma unroll
    for (int i = 0; i < 2; i++)
        #pragma unroll
        for (int jj = 0; jj < 4; jj++)
            wmma::fill_fragment(cf[i][jj], 0.0f);

    auto load_stage = [&](int st, int k0) {
        __half* Ad = hsm + st * STAGE_HALVES;
        __half* Bd = Ad + BM * ASTRIDE_H;
        #pragma unroll
        for (int i = 0; i < 2; i++) {
            int idx = tid + i * 256;
            int r = idx >> 2, c = (idx & 3) * 8;
            cp16(&Ad[r * ASTRIDE_H + c], Abase + (long)r * E_DIM + k0 + c);
        }
        #pragma unroll
        for (int i = 0; i < 2; i++) {
            int idx = tid + i * 256;
            int r = idx >> 4, c = (idx & 15) * 8;
            cp16(&Bd[r * BSTRIDE_H + c], g_w1h + (long)(k0 + r) * G1 + bn * BN + c);
        }
        CP_COMMIT();
    };

    load_stage(0, 0);
    load_stage(1, BK);

    const int NKT = E_DIM / BK;
    int st = 0;
    for (int kt = 0; kt < NKT; kt++) {
        if (kt < NKT - 1) asm volatile("cp.async.wait_group 1;\n" ::);
        else              asm volatile("cp.async.wait_group 0;\n" ::);
        __syncthreads();

        if (kt + 2 < NKT) {
            int st2 = st + 2; if (st2 >= 3) st2 -= 3;
            load_stage(st2, (kt + 2) * BK);
        }

        const __half* Ac = hsm + st * STAGE_HALVES;
        const __half* Bc = Ac + BM * ASTRIDE_H;
        #pragma unroll
        for (int kk = 0; kk < 2; kk++) {
            wmma::fragment<wmma::matrix_a, 16, 16, 16, __half, wmma::row_major> af[2];
            #pragma unroll
            for (int i = 0; i < 2; i++)
                wmma::load_matrix_sync(af[i], &Ac[(wm * 32 + i * 16) * ASTRIDE_H + kk * 16], ASTRIDE_H);
            #pragma unroll
            for (int jj = 0; jj < 4; jj++) {
                wmma::fragment<wmma::matrix_b, 16, 16, 16, __half, wmma::row_major> bf;
                wmma::load_matrix_sync(bf, &Bc[(kk * 16) * BSTRIDE_H + wn * 64 + jj * 16], BSTRIDE_H);
                #pragma unroll
                for (int i = 0; i < 2; i++)
                    wmma::mma_sync(cf[i][jj], af[i], bf, cf[i][jj]);
            }
        }
        if (++st >= 3) st -= 3;
    }

    #pragma unroll
    for (int i = 0; i < 2; i++)
        #pragma unroll
        for (int jj = 0; jj < 4; jj++) {
            float* dst = &g_xw1[(row0 + wm * 32 + i * 16) * (long)G1 + bn * BN + wn * 64 + jj * 16];
            wmma::store_matrix_sync(dst, cf[i][jj], G1, wmma::mem_row_major);
        }
}

// =====================================================================
// Kernel 2: tensor-core LSTM with U1 B-FRAGMENTS PINNED IN REGISTERS.
// Each warp loads its 8 U1 fragments (N-tile = warp*32) ONCE before the
// time loop -> zero global loads inside the recurrence. Wc stays in smem.
// smem (bytes): Wch 101376 | zA 16384 | zBp 16384 | hB 3200 | h2f 2048
// =====================================================================
#define HBLD 200   // hB row stride in halves
#define WLD  264   // Wch row stride in halves
#define OFF_ZA   101376
#define OFF_ZBP  117760
#define OFF_HB   134144
#define OFF_H2F  137344
#define LSTM_SMEM_BYTES 139392

__global__ __launch_bounds__(LSTM_THREADS, 1) void lstm_kernel(
    const float* __restrict__ b1,
    const float* __restrict__ b2)
{
    extern __shared__ char smx[];
    __half* Wch = (__half*)smx;
    float*  zA  = (float*)(smx + OFF_ZA);    // [8][512]
    float*  zBp = (float*)(smx + OFF_ZBP);   // [2][8][256]
    __half* hB  = (__half*)(smx + OFF_HB);   // [8][HBLD]
    float*  h2f = (float*)(smx + OFF_H2F);   // [8][64]

    const int tid  = threadIdx.x;
    const int warp = tid >> 5;
    const long qbase = (long)blockIdx.x * SEQ_PER_BLOCK;

    // load Wc into smem
    for (int i = tid; i < 192 * 32; i += LSTM_THREADS) {
        int r = i >> 5, c = (i & 31) * 8;
        *(uint4*)&Wch[r * WLD + c] = *(const uint4*)&g_wch[r * G2 + c];
    }
    // zero h2 region + shadow
    {
        int s = tid >> 6, n = tid & 63;
        hB[s * HBLD + 128 + n] = __float2half(0.0f);
        h2f[s * 64 + n] = 0.0f;
    }

    // ---- pin U1 B-fragments in registers (loop-invariant) ----
    wmma::fragment<wmma::matrix_b, 8, 32, 16, __half, wmma::row_major> u1f[8];
    #pragma unroll
    for (int ks = 0; ks < 8; ks++)
        wmma::load_matrix_sync(u1f[ks], g_u1h + (ks * 16) * G1 + warp * 32, G1);

    // update-thread mappings
    const int p0s = tid >> 7, p0n = tid & 127;
    const int p1s = p0s + 4;
    const int u2s = tid >> 6, u2n = tid & 63;

    float c1a = 0.0f, c1b = 0.0f, c2 = 0.0f;

    const float b1i = b1[p0n], b1f = b1[128 + p0n],
                b1g = b1[256 + p0n], b1o = b1[384 + p0n];
    const float b2i = b2[u2n], b2f = b2[64 + u2n],
                b2g = b2[128 + u2n], b2o = b2[192 + u2n];

    __syncthreads();

    // ---- prologue: h1(0) from xw(0)+b1 ----
    {
        const float* xp = g_xw1 + ((qbase + p0s) * T_LEN) * (long)G1;
        float zi = xp[p0n] + b1i;
        float zg = xp[256 + p0n] + b1g, zo = xp[384 + p0n] + b1o;
        c1a = fsig(zi) * tanh_ap(zg);
        hB[p0s * HBLD + p0n] = __float2half(fsig(zo) * tanh_ap(c1a));
    }
    {
        const float* xp = g_xw1 + ((qbase + p1s) * T_LEN) * (long)G1;
        float zi = xp[p0n] + b1i;
        float zg = xp[256 + p0n] + b1g, zo = xp[384 + p0n] + b1o;
        c1b = fsig(zi) * tanh_ap(zg);
        hB[p1s * HBLD + p0n] = __float2half(fsig(zo) * tanh_ap(c1b));
    }
    __syncthreads();

    const int btile = warp >> 1;     // Phase B N-tile (0..7)
    const int kh    = warp & 1;      // Phase B K-half

    for (int t = 0; t < T_LEN; t++) {
        const bool notlast = (t < T_LEN - 1);

        // ================= MMA phase =================
        // Phase A: z1(t+1), N-tile = warp*32; U1 frags from registers
        {
            wmma::fragment<wmma::accumulator, 8, 32, 16, float> acc;
            wmma::fill_fragment(acc, 0.0f);
            #pragma unroll
            for (int ks = 0; ks < 8; ks++) {
                wmma::fragment<wmma::matrix_a, 8, 32, 16, __half, wmma::row_major> af;
                wmma::load_matrix_sync(af, hB + ks * 16, HBLD);
                wmma::mma_sync(acc, af, u1f[ks], acc);
            }
            wmma::store_matrix_sync(zA + warp * 32, acc, G1, wmma::mem_row_major);
        }
        // Phase B: z2(t) K-half partial, N-tile = btile*32 (Wc from smem)
        {
            wmma::fragment<wmma::accumulator, 8, 32, 16, float> acc;
            wmma::fill_fragment(acc, 0.0f);
            #pragma unroll
            for (int ks = 0; ks < 6; ks++) {
                int k0 = kh * 96 + ks * 16;
                wmma::fragment<wmma::matrix_a, 8, 32, 16, __half, wmma::row_major> af;
                wmma::load_matrix_sync(af, hB + k0, HBLD);
                wmma::fragment<wmma::matrix_b, 8, 32, 16, __half, wmma::row_major> bf;
                wmma::load_matrix_sync(bf, Wch + k0 * WLD + btile * 32, WLD);
                wmma::mma_sync(acc, af, bf, acc);
            }
            wmma::store_matrix_sync(zBp + kh * (8 * G2) + btile * 32, acc, G2,
                                    wmma::mem_row_major);
        }
        __syncthreads();

        // ================= update phase =================
        // update2(t): h2(t), c2
        {
            const float* z0 = zBp + u2s * G2 + u2n;
            const float* z1 = z0 + 8 * G2;
            float zi = z0[0]   + z1[0]   + b2i;
            float zf = z0[64]  + z1[64]  + b2f;
            float zg = z0[128] + z1[128] + b2g;
            float zo = z0[192] + z1[192] + b2o;
            c2 = fsig(zf) * c2 + fsig(zi) * tanh_ap(zg);
            float h = fsig(zo) * tanh_ap(c2);
            hB[u2s * HBLD + 128 + u2n] = __float2half(h);
            h2f[u2s * 64 + u2n] = h;
        }
        // update1(t+1): h1(t+1), c1
        if (notlast) {
            {
                const float* xp = g_xw1 + ((qbase + p0s) * T_LEN + t + 1) * (long)G1;
                const float* za = zA + p0s * G1;
                float zi = za[p0n]       + xp[p0n]       + b1i;
                float zf = za[128 + p0n] + xp[128 + p0n] + b1f;
                float zg = za[256 + p0n] + xp[256 + p0n] + b1g;
                float zo = za[384 + p0n] + xp[384 + p0n] + b1o;
                c1a = fsig(zf) * c1a + fsig(zi) * tanh_ap(zg);
                hB[p0s * HBLD + p0n] = __float2half(fsig(zo) * tanh_ap(c1a));
            }
            {
                const float* xp = g_xw1 + ((qbase + p1s) * T_LEN + t + 1) * (long)G1;
                const float* za = zA + p1s * G1;
                float zi = za[p0n]       + xp[p0n]       + b1i;
                float zf = za[128 + p0n] + xp[128 + p0n] + b1f;
                float zg = za[256 + p0n] + xp[256 + p0n] + b1g;
                float zo = za[384 + p0n] + xp[384 + p0n] + b1o;
                c1b = fsig(zf) * c1b + fsig(zi) * tanh_ap(zg);
                hB[p1s * HBLD + p0n] = __float2half(fsig(zo) * tanh_ap(c1b));
            }
        }
        __syncthreads();
    }

    g_enc[(qbase + u2s) * H2 + u2n] = h2f[u2s * 64 + u2n];
}

// =====================================================================
// Kernel 3: ALL heads in one launch (unchanged)
// =====================================================================
__global__ __launch_bounds__(128) void heads_kernel(
    const float* __restrict__ W1h_, const float* __restrict__ b1h,
    const float* __restrict__ g1h, const float* __restrict__ be1,
    const float* __restrict__ m1h, const float* __restrict__ v1h,
    const float* __restrict__ W2h, const float* __restrict__ b2h,
    const float* __restrict__ g2h, const float* __restrict__ be2,
    const float* __restrict__ m2h, const float* __restrict__ v2h,
    const float* __restrict__ W3h, const float* __restrict__ b3h,
    const float* __restrict__ g3h, const float* __restrict__ be3,
    const float* __restrict__ m3h, const float* __restrict__ v3h,
    float* __restrict__ out)
{
    __shared__ float x[128];
    const int row = blockIdx.x;
    const int tid = threadIdx.x;

    const float *W, *b, *g, *beta, *m, *v;
    int bidx;
    if (row < 200)      { W = W1h_; b = b1h; g = g1h; beta = be1; m = m1h; v = v1h; bidx = row / 25; }
    else if (row < 400) { W = W2h; b = b2h; g = g2h; beta = be2; m = m2h; v = v2h; bidx = (row - 200) / 25; }
    else                { W = W3h; b = b3h; g = g3h; beta = be3; m = m3h; v = v3h; bidx = (row - 400) / 64; }

    if (tid < 64) x[tid] = g_enc[row * H2 + tid];
    else          x[tid] = g_enc[(912 + bidx) * H2 + (tid - 64)];
    __syncthreads();

    if (tid < 32) {
        float acc = b[tid];
        #pragma unroll 8
        for (int k = 0; k < 128; k++) acc = fmaf(x[k], W[k * 32 + tid], acc);
        float y = fmaxf(acc, 0.0f);
        out[row * 32 + tid] = g[tid] * (y - m[tid]) * rsqrtf(v[tid] + 1e-3f) + beta[tid];
    }
}

// =====================================================================
extern "C" void kernel_launch(void* const* d_in, const int* in_sizes, int n_in,
                              void* d_out, int out_size)
{
    (void)in_sizes; (void)n_in; (void)out_size;

    const float* support = (const float*)d_in[0];
    const float* query   = (const float*)d_in[1];
    const float* unlabel = (const float*)d_in[2];
    const float* model   = (const float*)d_in[3];
    const float* W1 = (const float*)d_in[4];
    const float* U1 = (const float*)d_in[5];
    const float* b1 = (const float*)d_in[6];
    const float* W2 = (const float*)d_in[7];
    const float* U2 = (const float*)d_in[8];
    const float* b2 = (const float*)d_in[9];
    float* out = (float*)d_out;

    // Phase 0: fp16 conversions
    convert_x<<<44160, 256>>>(support, query, unlabel, model);
    convert_w<<<192, 256>>>(W1);
    convert_rec<<<56, 256>>>(U1, W2, U2);

    // Phase 1: fp16 WMMA GEMM
    cudaFuncSetAttribute(gemm1_kernel,
                         cudaFuncAttributeMaxDynamicSharedMemorySize,
                         GEMM_SMEM_BYTES);
    dim3 ggrid(G1 / BN, MROWS / BM);   // (4, 920)
    gemm1_kernel<<<ggrid, 256, GEMM_SMEM_BYTES>>>();

    // Phase 2: tensor-core LSTM (U1 frags pinned in registers)
    cudaFuncSetAttribute(lstm_kernel,
                         cudaFuncAttributeMaxDynamicSharedMemorySize,
                         LSTM_SMEM_BYTES);
    lstm_kernel<<<NSEQ / SEQ_PER_BLOCK, LSTM_THREADS, LSTM_SMEM_BYTES>>>(b1, b2);

    // Phase 3: heads
    heads_kernel<<<912, 128>>>(
        (const float*)d_in[10], (const float*)d_in[11], (const float*)d_in[12],
        (const float*)d_in[13], (const float*)d_in[14], (const float*)d_in[15],
        (const float*)d_in[16], (const float*)d_in[17], (const float*)d_in[18],
        (const float*)d_in[19], (const float*)d_in[20], (const float*)d_in[21],
        (const float*)d_in[22], (const float*)d_in[23], (const float*)d_in[24],
        (const float*)d_in[25], (const float*)d_in[26], (const float*)d_in[27],
        out);
}